// round 1
// baseline (speedup 1.0000x reference)
#include <cuda_runtime.h>
#include <math.h>

#define B   64
#define C   256
#define N   20000
#define NPAD 20032          // 313 * 64
#define NT  64
#define KTOP 8
#define PAGE (NT*C)         // 16384 floats per template page
#define GATE_OFF (B*KTOP*NT*C)   // 8388608 : tokens, then gate per batch

// ---- device scratch (allocation-free rule: __device__ globals) ----
__device__ float g_qn[B*C];
__device__ float g_sims[B*NPAD];
__device__ int   g_topidx[B*KTOP];

// ============================================================================
// Kernel 1: normalize queries; also emit gate outputs
// ============================================================================
__global__ void prep_kernel(const float* __restrict__ q,
                            const float* __restrict__ gate_logit,
                            float* __restrict__ out)
{
    int tid  = threadIdx.x;
    int lane = tid & 31;
    int w    = tid >> 5;   // 8 warps
    for (int r = w; r < B; r += 8) {
        const float4* qr = (const float4*)(q + r * C);
        float4 a = qr[lane*2];
        float4 b = qr[lane*2 + 1];
        float ss = a.x*a.x + a.y*a.y + a.z*a.z + a.w*a.w
                 + b.x*b.x + b.y*b.y + b.z*b.z + b.w*b.w;
        #pragma unroll
        for (int o = 16; o > 0; o >>= 1) ss += __shfl_xor_sync(0xffffffffu, ss, o);
        float inv = 1.0f / fmaxf(sqrtf(ss), 1e-12f);
        float4* dst = (float4*)(g_qn + r * C);
        a.x *= inv; a.y *= inv; a.z *= inv; a.w *= inv;
        b.x *= inv; b.y *= inv; b.z *= inv; b.w *= inv;
        dst[lane*2]     = a;
        dst[lane*2 + 1] = b;
    }
    if (tid < B) {
        float gl   = gate_logit[0];
        float gate = 1.0f / (1.0f + expf(-gl));
        out[GATE_OFF + tid] = gate;
    }
}

// ============================================================================
// Kernel 2: sims = qn @ norm(summaries)^T   (64 x NPAD), tile 64 summaries/block
// ============================================================================
#define SQ_STRIDE 260   // 256 + 4 pad (float4-aligned)

extern __shared__ float s_sims[];

__global__ __launch_bounds__(256) void sims_kernel(const float* __restrict__ summ)
{
    float* qs   = s_sims;                       // [64][260]
    float* ssm  = qs  + 64 * SQ_STRIDE;         // [64][260]
    float* sinv = ssm + 64 * SQ_STRIDE;         // [64]

    int tid = threadIdx.x;
    int n0  = blockIdx.x * 64;

    // load normalized queries (64 x 256)
    for (int i = tid; i < 64 * 64; i += 256) {
        int row = i >> 6, col = i & 63;
        float4 v = ((const float4*)g_qn)[row * 64 + col];
        *(float4*)(qs + row * SQ_STRIDE + col * 4) = v;
    }
    // load summary tile (bounds-checked)
    for (int i = tid; i < 64 * 64; i += 256) {
        int row = i >> 6, col = i & 63;
        int n = n0 + row;
        float4 v = make_float4(0.f, 0.f, 0.f, 0.f);
        if (n < N) v = ((const float4*)summ)[n * 64 + col];
        *(float4*)(ssm + row * SQ_STRIDE + col * 4) = v;
    }
    __syncthreads();

    // per-row inverse norms (8 warps x 8 rows)
    int lane = tid & 31, w = tid >> 5;
    for (int r = w; r < 64; r += 8) {
        float4 a = *(float4*)(ssm + r * SQ_STRIDE + lane * 8);
        float4 b = *(float4*)(ssm + r * SQ_STRIDE + lane * 8 + 4);
        float ss = a.x*a.x + a.y*a.y + a.z*a.z + a.w*a.w
                 + b.x*b.x + b.y*b.y + b.z*b.z + b.w*b.w;
        #pragma unroll
        for (int o = 16; o > 0; o >>= 1) ss += __shfl_xor_sync(0xffffffffu, ss, o);
        if (lane == 0) sinv[r] = 1.0f / fmaxf(sqrtf(ss), 1e-12f);
    }
    __syncthreads();

    int tx = tid & 15, ty = tid >> 4;
    float acc[4][4];
    #pragma unroll
    for (int r = 0; r < 4; r++)
        #pragma unroll
        for (int c = 0; c < 4; c++) acc[r][c] = 0.0f;

    for (int kk = 0; kk < 256; kk += 4) {
        float4 qf[4];
        #pragma unroll
        for (int r = 0; r < 4; r++)
            qf[r] = *(float4*)(qs + (r * 16 + ty) * SQ_STRIDE + kk);
        #pragma unroll
        for (int c = 0; c < 4; c++) {
            float4 sf = *(float4*)(ssm + (c * 16 + tx) * SQ_STRIDE + kk);
            #pragma unroll
            for (int r = 0; r < 4; r++) {
                acc[r][c] += qf[r].x * sf.x;
                acc[r][c] += qf[r].y * sf.y;
                acc[r][c] += qf[r].z * sf.z;
                acc[r][c] += qf[r].w * sf.w;
            }
        }
    }

    #pragma unroll
    for (int r = 0; r < 4; r++) {
        int b = r * 16 + ty;
        #pragma unroll
        for (int c = 0; c < 4; c++) {
            int nl = c * 16 + tx;
            int n  = n0 + nl;
            float v = (n < N) ? acc[r][c] * sinv[nl] : -INFINITY;
            g_sims[b * NPAD + n] = v;
        }
    }
}

// ============================================================================
// Kernel 3: top-8 per query (jax.lax.top_k semantics: desc, ties -> lower idx)
// ============================================================================
__device__ __forceinline__ bool tk_better(float v1, int i1, float v2, int i2)
{
    return (v1 > v2) || (v1 == v2 && i1 < i2);
}

__global__ __launch_bounds__(256) void topk_kernel()
{
    __shared__ float cv[2048];
    __shared__ int   ci[2048];
    __shared__ float rv[256];
    __shared__ int   ri[256];

    int b = blockIdx.x, tid = threadIdx.x;
    const float* row = g_sims + (size_t)b * NPAD;

    float lv[KTOP]; int li[KTOP];
    #pragma unroll
    for (int j = 0; j < KTOP; j++) { lv[j] = -INFINITY; li[j] = 0x7fffffff; }

    for (int n = tid; n < NPAD; n += 256) {
        float v = row[n];
        if (tk_better(v, n, lv[KTOP-1], li[KTOP-1])) {
            int p = KTOP - 1;
            #pragma unroll
            for (int j = KTOP - 1; j > 0; j--) {
                if (tk_better(v, n, lv[j-1], li[j-1])) {
                    lv[j] = lv[j-1]; li[j] = li[j-1]; p = j - 1;
                } else break;
            }
            lv[p] = v; li[p] = n;
        }
    }
    #pragma unroll
    for (int j = 0; j < KTOP; j++) { cv[tid*KTOP + j] = lv[j]; ci[tid*KTOP + j] = li[j]; }
    __syncthreads();

    for (int sel = 0; sel < KTOP; sel++) {
        float bv = -INFINITY; int bi = 0x7fffffff;
        #pragma unroll
        for (int j = 0; j < KTOP; j++) {
            float v = cv[tid*KTOP + j]; int i = ci[tid*KTOP + j];
            if (tk_better(v, i, bv, bi)) { bv = v; bi = i; }
        }
        rv[tid] = bv; ri[tid] = bi;
        __syncthreads();
        for (int s = 128; s > 0; s >>= 1) {
            if (tid < s) {
                if (tk_better(rv[tid+s], ri[tid+s], rv[tid], ri[tid])) {
                    rv[tid] = rv[tid+s]; ri[tid] = ri[tid+s];
                }
            }
            __syncthreads();
        }
        int win = ri[0];
        if (tid == 0) g_topidx[b * KTOP + sel] = win;
        #pragma unroll
        for (int j = 0; j < KTOP; j++) {
            if (ci[tid*KTOP + j] == win) cv[tid*KTOP + j] = -INFINITY;
        }
        __syncthreads();
    }
}

// ============================================================================
// Kernel 4: gather page -> h = x @ W^T + b -> LayerNorm -> * gate -> out
// One block per (b, k) page: M=64 rows, N=256 cols, K=256.
// Thread (ty, tx): rows r*16+ty (r<4), cols cj*16+tx (cj<16)
// ============================================================================
#define KC  64
#define WST 68
#define XST 68

extern __shared__ float s_fused[];

__global__ __launch_bounds__(256, 2) void fused_kernel(
    const float* __restrict__ templates,
    const float* __restrict__ wproj,
    const float* __restrict__ bproj,
    const float* __restrict__ gamma_g,
    const float* __restrict__ beta_g,
    const float* __restrict__ gate_logit,
    float* __restrict__ out)
{
    float* xs  = s_fused;               // [64][68]
    float* ws  = xs + 64 * XST;         // [256][68]
    float* gam = ws + 256 * WST;        // [256]
    float* bet = gam + 256;
    float* bia = bet + 256;

    int tid = threadIdx.x;
    int bk  = blockIdx.x;               // b*8 + k
    int page = g_topidx[bk];
    const float* x = templates + (size_t)page * PAGE;

    if (tid < 256) { gam[tid] = gamma_g[tid]; bet[tid] = beta_g[tid]; bia[tid] = bproj[tid]; }

    int tx = tid & 15, ty = tid >> 4;
    float acc[4][16];
    #pragma unroll
    for (int r = 0; r < 4; r++)
        #pragma unroll
        for (int c = 0; c < 16; c++) acc[r][c] = 0.0f;

    for (int kt = 0; kt < 4; kt++) {
        int k0 = kt * KC;
        // x chunk: 64 rows x 16 float4
        for (int i = tid; i < 64 * 16; i += 256) {
            int row = i >> 4, c4 = i & 15;
            float4 v = *(const float4*)(x + row * C + k0 + c4 * 4);
            *(float4*)(xs + row * XST + c4 * 4) = v;
        }
        // W chunk: 256 rows x 16 float4
        for (int i = tid; i < 256 * 16; i += 256) {
            int row = i >> 4, c4 = i & 15;
            float4 v = *(const float4*)(wproj + row * C + k0 + c4 * 4);
            *(float4*)(ws + row * WST + c4 * 4) = v;
        }
        __syncthreads();

        #pragma unroll
        for (int kk = 0; kk < KC; kk += 4) {
            float4 xf[4];
            #pragma unroll
            for (int r = 0; r < 4; r++)
                xf[r] = *(float4*)(xs + (r * 16 + ty) * XST + kk);
            #pragma unroll
            for (int cj = 0; cj < 16; cj++) {
                float4 wf = *(float4*)(ws + (cj * 16 + tx) * WST + kk);
                #pragma unroll
                for (int r = 0; r < 4; r++) {
                    acc[r][cj] += xf[r].x * wf.x;
                    acc[r][cj] += xf[r].y * wf.y;
                    acc[r][cj] += xf[r].z * wf.z;
                    acc[r][cj] += xf[r].w * wf.w;
                }
            }
        }
        __syncthreads();
    }

    // epilogue: bias + LayerNorm + gate
    float gate = 1.0f / (1.0f + expf(-gate_logit[0]));
    #pragma unroll
    for (int r = 0; r < 4; r++) {
        float s1 = 0.f, s2 = 0.f;
        #pragma unroll
        for (int cj = 0; cj < 16; cj++) {
            float h = acc[r][cj] + bia[cj * 16 + tx];
            acc[r][cj] = h;
            s1 += h;
            s2 += h * h;
        }
        // reduce across the 16 tx threads of this row (xor 1,2,4,8 stays in half-warp)
        #pragma unroll
        for (int o = 8; o > 0; o >>= 1) {
            s1 += __shfl_xor_sync(0xffffffffu, s1, o);
            s2 += __shfl_xor_sync(0xffffffffu, s2, o);
        }
        float mu   = s1 * (1.0f / 256.0f);
        float var  = s2 * (1.0f / 256.0f) - mu * mu;
        float rstd = rsqrtf(var + 1e-5f);

        int grow = bk * 64 + (r * 16 + ty);      // token row within (B, K*Nt)
        float* orow = out + (size_t)grow * C;
        #pragma unroll
        for (int cj = 0; cj < 16; cj++) {
            int col = cj * 16 + tx;
            float t = (acc[r][cj] - mu) * rstd * gam[col] + bet[col];
            orow[col] = t * gate;
        }
    }
}

// ============================================================================
// launch
// ============================================================================
extern "C" void kernel_launch(void* const* d_in, const int* in_sizes, int n_in,
                              void* d_out, int out_size)
{
    const float* query = (const float*)d_in[0];
    const float* summ  = (const float*)d_in[1];
    const float* templ = (const float*)d_in[2];
    const float* wproj = (const float*)d_in[3];
    const float* bproj = (const float*)d_in[4];
    const float* gamma = (const float*)d_in[5];
    const float* beta  = (const float*)d_in[6];
    const float* glog  = (const float*)d_in[7];
    float* out = (float*)d_out;

    const int SIMS_SMEM  = (2 * 64 * SQ_STRIDE + 64) * sizeof(float);       // ~133 KB
    const int FUSED_SMEM = (64 * XST + 256 * WST + 3 * 256) * sizeof(float); // ~90 KB

    cudaFuncSetAttribute(sims_kernel,  cudaFuncAttributeMaxDynamicSharedMemorySize, SIMS_SMEM);
    cudaFuncSetAttribute(fused_kernel, cudaFuncAttributeMaxDynamicSharedMemorySize, FUSED_SMEM);

    prep_kernel<<<1, 256>>>(query, glog, out);
    sims_kernel<<<NPAD / 64, 256, SIMS_SMEM>>>(summ);
    topk_kernel<<<B, 256>>>();
    fused_kernel<<<B * KTOP, 256, FUSED_SMEM>>>(templ, wproj, bproj, gamma, beta, glog, out);
}

// round 3
// speedup vs baseline: 1.4994x; 1.4994x over previous
#include <cuda_runtime.h>
#include <cuda_bf16.h>
#include <math.h>
#include <stdint.h>

#define B   64
#define C   256
#define N   20000
#define NPAD 20032          // 313 * 64
#define NT  64
#define KTOP 8
#define PAGE (NT*C)         // 16384 floats per template page
#define GATE_OFF (B*KTOP*NT*C)

// ---- device scratch ----
__device__ float g_qn[B*C];
__device__ float g_sims[B*NPAD];
__device__ int   g_topidx[B*KTOP];
__device__ float g_cand_v[B*32];
__device__ int   g_cand_i[B*32];
__device__ uint4 g_Whi4[8192];   // 4 chunk-tiles of 256 rows x 64 bf16 (128B rows, XOR-swizzled)
__device__ uint4 g_Wlo4[8192];

#define SW128(b) ((b) ^ (((b) >> 3) & 0x70))

__device__ __forceinline__ uint32_t smem_u32(const void* p) {
    uint32_t a;
    asm("{ .reg .u64 t; cvta.to.shared.u64 t, %1; cvt.u32.u64 %0, t; }" : "=r"(a) : "l"(p));
    return a;
}

__device__ __forceinline__ void ldsm_x4(uint32_t* r, uint32_t addr) {
    asm volatile("ldmatrix.sync.aligned.m8n8.x4.shared.b16 {%0,%1,%2,%3}, [%4];"
                 : "=r"(r[0]), "=r"(r[1]), "=r"(r[2]), "=r"(r[3]) : "r"(addr));
}

__device__ __forceinline__ void mma_bf16(float* c, const uint32_t* a, const uint32_t* b) {
    asm volatile(
        "mma.sync.aligned.m16n8k16.row.col.f32.bf16.bf16.f32 "
        "{%0,%1,%2,%3}, {%4,%5,%6,%7}, {%8,%9}, {%0,%1,%2,%3};"
        : "+f"(c[0]), "+f"(c[1]), "+f"(c[2]), "+f"(c[3])
        : "r"(a[0]), "r"(a[1]), "r"(a[2]), "r"(a[3]), "r"(b[0]), "r"(b[1]));
}

// ============================================================================
// Kernel 1: normalize queries; emit gate outputs
// ============================================================================
__global__ void prep_kernel(const float* __restrict__ q,
                            const float* __restrict__ gate_logit,
                            float* __restrict__ out)
{
    int tid = threadIdx.x, lane = tid & 31, w = tid >> 5;
    for (int r = w; r < B; r += 8) {
        const float4* qr = (const float4*)(q + r * C);
        float4 a = qr[lane*2], b = qr[lane*2 + 1];
        float ss = a.x*a.x + a.y*a.y + a.z*a.z + a.w*a.w
                 + b.x*b.x + b.y*b.y + b.z*b.z + b.w*b.w;
        #pragma unroll
        for (int o = 16; o > 0; o >>= 1) ss += __shfl_xor_sync(0xffffffffu, ss, o);
        float inv = 1.0f / fmaxf(sqrtf(ss), 1e-12f);
        float4* dst = (float4*)(g_qn + r * C);
        a.x*=inv; a.y*=inv; a.z*=inv; a.w*=inv;
        b.x*=inv; b.y*=inv; b.z*=inv; b.w*=inv;
        dst[lane*2] = a; dst[lane*2 + 1] = b;
    }
    if (tid < B) {
        float gate = 1.0f / (1.0f + expf(-gate_logit[0]));
        out[GATE_OFF + tid] = gate;
    }
}

// ============================================================================
// Kernel 1b: W -> bf16 hi/lo, chunk-tiled (k/64), 128B rows, XOR swizzle
// ============================================================================
__global__ void wprep_kernel(const float* __restrict__ wproj)
{
    int p = blockIdx.x * 256 + threadIdx.x;   // 32768 pairs
    int row = p >> 7, pp = p & 127;
    int k = pp * 2, chunk = pp >> 5, kc = k & 63;
    float2 v = *(const float2*)(wproj + row * C + k);
    __nv_bfloat16 h0 = __float2bfloat16(v.x), h1 = __float2bfloat16(v.y);
    float r0 = v.x - __bfloat162float(h0), r1 = v.y - __bfloat162float(h1);
    __nv_bfloat16 l0 = __float2bfloat16(r0), l1 = __float2bfloat16(r1);
    uint32_t hp = (uint32_t)__bfloat16_as_ushort(h0) | ((uint32_t)__bfloat16_as_ushort(h1) << 16);
    uint32_t lp = (uint32_t)__bfloat16_as_ushort(l0) | ((uint32_t)__bfloat16_as_ushort(l1) << 16);
    uint32_t off = (uint32_t)SW128(row * 128 + kc * 2);
    uint32_t idx = (uint32_t)chunk * 8192u + (off >> 2);
    ((uint32_t*)g_Whi4)[idx] = hp;
    ((uint32_t*)g_Wlo4)[idx] = lp;
}

// ============================================================================
// Kernel 2: sims = qn @ norm(summaries)^T
// ============================================================================
#define SQ_STRIDE 260
extern __shared__ float s_sims[];

__global__ __launch_bounds__(256) void sims_kernel(const float* __restrict__ summ)
{
    float* qs   = s_sims;
    float* ssm  = qs  + 64 * SQ_STRIDE;
    float* sinv = ssm + 64 * SQ_STRIDE;

    int tid = threadIdx.x;
    int n0  = blockIdx.x * 64;

    for (int i = tid; i < 64 * 64; i += 256) {
        int row = i >> 6, col = i & 63;
        float4 v = ((const float4*)g_qn)[row * 64 + col];
        *(float4*)(qs + row * SQ_STRIDE + col * 4) = v;
    }
    for (int i = tid; i < 64 * 64; i += 256) {
        int row = i >> 6, col = i & 63;
        int n = n0 + row;
        float4 v = make_float4(0.f, 0.f, 0.f, 0.f);
        if (n < N) v = ((const float4*)summ)[n * 64 + col];
        *(float4*)(ssm + row * SQ_STRIDE + col * 4) = v;
    }
    __syncthreads();

    int lane = tid & 31, w = tid >> 5;
    for (int r = w; r < 64; r += 8) {
        float4 a = *(float4*)(ssm + r * SQ_STRIDE + lane * 8);
        float4 b = *(float4*)(ssm + r * SQ_STRIDE + lane * 8 + 4);
        float ss = a.x*a.x + a.y*a.y + a.z*a.z + a.w*a.w
                 + b.x*b.x + b.y*b.y + b.z*b.z + b.w*b.w;
        #pragma unroll
        for (int o = 16; o > 0; o >>= 1) ss += __shfl_xor_sync(0xffffffffu, ss, o);
        if (lane == 0) sinv[r] = 1.0f / fmaxf(sqrtf(ss), 1e-12f);
    }
    __syncthreads();

    int tx = tid & 15, ty = tid >> 4;
    float acc[4][4];
    #pragma unroll
    for (int r = 0; r < 4; r++)
        #pragma unroll
        for (int c = 0; c < 4; c++) acc[r][c] = 0.0f;

    for (int kk = 0; kk < 256; kk += 4) {
        float4 qf[4];
        #pragma unroll
        for (int r = 0; r < 4; r++)
            qf[r] = *(float4*)(qs + (r * 16 + ty) * SQ_STRIDE + kk);
        #pragma unroll
        for (int c = 0; c < 4; c++) {
            float4 sf = *(float4*)(ssm + (c * 16 + tx) * SQ_STRIDE + kk);
            #pragma unroll
            for (int r = 0; r < 4; r++) {
                acc[r][c] += qf[r].x * sf.x;
                acc[r][c] += qf[r].y * sf.y;
                acc[r][c] += qf[r].z * sf.z;
                acc[r][c] += qf[r].w * sf.w;
            }
        }
    }

    #pragma unroll
    for (int r = 0; r < 4; r++) {
        int b = r * 16 + ty;
        #pragma unroll
        for (int c = 0; c < 4; c++) {
            int nl = c * 16 + tx;
            int n  = n0 + nl;
            float v = (n < N) ? acc[r][c] * sinv[nl] : -INFINITY;
            g_sims[b * NPAD + n] = v;
        }
    }
}

// ============================================================================
// Kernel 3a: partial top-8 per (query, quarter)  — 256 blocks
// ============================================================================
__device__ __forceinline__ bool tk_better(float v1, int i1, float v2, int i2)
{
    return (v1 > v2) || (v1 == v2 && i1 < i2);
}

__global__ __launch_bounds__(256) void topk_part_kernel()
{
    __shared__ float cv[2048];
    __shared__ int   ci[2048];
    __shared__ float rv[256];
    __shared__ int   ri[256];

    int b = blockIdx.x >> 2, part = blockIdx.x & 3, tid = threadIdx.x;
    const float* row = g_sims + (size_t)b * NPAD;
    int n_beg = part * 5008, n_end = n_beg + 5008;

    float lv[KTOP]; int li[KTOP];
    #pragma unroll
    for (int j = 0; j < KTOP; j++) { lv[j] = -INFINITY; li[j] = 0x7fffffff; }

    for (int n = n_beg + tid; n < n_end; n += 256) {
        float v = row[n];
        if (tk_better(v, n, lv[KTOP-1], li[KTOP-1])) {
            int p = KTOP - 1;
            #pragma unroll
            for (int j = KTOP - 1; j > 0; j--) {
                if (tk_better(v, n, lv[j-1], li[j-1])) {
                    lv[j] = lv[j-1]; li[j] = li[j-1]; p = j - 1;
                } else break;
            }
            lv[p] = v; li[p] = n;
        }
    }
    #pragma unroll
    for (int j = 0; j < KTOP; j++) { cv[tid*KTOP + j] = lv[j]; ci[tid*KTOP + j] = li[j]; }
    __syncthreads();

    for (int sel = 0; sel < KTOP; sel++) {
        float bv = -INFINITY; int bi = 0x7fffffff;
        #pragma unroll
        for (int j = 0; j < KTOP; j++) {
            float v = cv[tid*KTOP + j]; int i = ci[tid*KTOP + j];
            if (tk_better(v, i, bv, bi)) { bv = v; bi = i; }
        }
        rv[tid] = bv; ri[tid] = bi;
        __syncthreads();
        for (int s = 128; s > 0; s >>= 1) {
            if (tid < s) {
                if (tk_better(rv[tid+s], ri[tid+s], rv[tid], ri[tid])) {
                    rv[tid] = rv[tid+s]; ri[tid] = ri[tid+s];
                }
            }
            __syncthreads();
        }
        int win = ri[0];
        if (tid == 0) {
            g_cand_v[b*32 + part*KTOP + sel] = rv[0];
            g_cand_i[b*32 + part*KTOP + sel] = win;
        }
        #pragma unroll
        for (int j = 0; j < KTOP; j++)
            if (ci[tid*KTOP + j] == win) cv[tid*KTOP + j] = -INFINITY;
        __syncthreads();
    }
}

// ============================================================================
// Kernel 3b: merge 32 candidates -> top-8 (one warp per query)
// ============================================================================
__global__ void topk_merge_kernel()
{
    int b = blockIdx.x, lane = threadIdx.x;
    float v   = g_cand_v[b*32 + lane];
    int   idx = g_cand_i[b*32 + lane];

    for (int sel = 0; sel < KTOP; sel++) {
        int s = __float_as_int(v);
        unsigned u = (unsigned)s ^ (unsigned)((s >> 31) | 0x80000000);
        unsigned long long key = ((unsigned long long)u << 32) | (unsigned)(0xffffffffu - (unsigned)idx);
        unsigned long long m = key;
        #pragma unroll
        for (int o = 16; o > 0; o >>= 1) {
            unsigned long long t = __shfl_xor_sync(0xffffffffu, m, o);
            if (t > m) m = t;
        }
        if (key == m) {
            g_topidx[b*KTOP + sel] = idx;
            v = -INFINITY; idx = 0x7fffffff;
        }
    }
}

// ============================================================================
// Kernel 4: mma.sync fused  gather -> (x@W^T + b) -> LN -> gate -> out
// Block: 512 threads (16 warps), M=128 (2 pages), N=256, K=256.
// x (hi/lo) fully smem-resident; W streamed in 4 chunks of K=64.
// Warp (wm = wid&3, wn = wid>>2): rows 32*wm..+32, cols 64*wn..+64.
// ============================================================================
#define SM_XHI   0              // 4 tiles x 16KB (128 rows x 128B)
#define SM_XLO   65536
#define SM_WHI   131072         // 256 rows x 128B = 32KB (current chunk)
#define SM_WLO   163840
#define SM_PAR   196608         // bias | gamma | beta (256 f32 each)
#define SM_RED   199680         // 4 x 128 float2
#define SM_TOTAL 203776

extern __shared__ char s_mm[];

__global__ __launch_bounds__(512, 1) void fused_mma_kernel(
    const float* __restrict__ templates,
    const float* __restrict__ bproj,
    const float* __restrict__ gamma_g,
    const float* __restrict__ beta_g,
    const float* __restrict__ gate_logit,
    float* __restrict__ out)
{
    uint32_t smb = smem_u32(s_mm);
    int tid = threadIdx.x, wid = tid >> 5, lane = tid & 31;
    int bid = blockIdx.x;
    int wm = wid & 3, wn = wid >> 2;

    float* biasS = (float*)(s_mm + SM_PAR);
    float* gamS  = biasS + 256;
    float* betS  = gamS + 256;
    float2* red2 = (float2*)(s_mm + SM_RED);   // [4][128]
    if (tid < 256) { biasS[tid] = bproj[tid]; gamS[tid] = gamma_g[tid]; betS[tid] = beta_g[tid]; }

    // ---- gather + convert x (2 pages = 128 rows x 256 k) into hi/lo tiles ----
    int p0 = g_topidx[2*bid], p1 = g_topidx[2*bid + 1];
    for (int i = tid; i < 16384; i += 512) {            // bf16 pairs
        int row = i >> 7, pp = i & 127;
        int k = pp * 2, chunk = pp >> 5, kc = k & 63;
        const float* src = templates + (size_t)(row < 64 ? p0 : p1) * PAGE + (row & 63) * C + k;
        float2 v = *(const float2*)src;
        __nv_bfloat16 h0 = __float2bfloat16(v.x), h1 = __float2bfloat16(v.y);
        float r0 = v.x - __bfloat162float(h0), r1 = v.y - __bfloat162float(h1);
        __nv_bfloat16 l0 = __float2bfloat16(r0), l1 = __float2bfloat16(r1);
        uint32_t hp = (uint32_t)__bfloat16_as_ushort(h0) | ((uint32_t)__bfloat16_as_ushort(h1) << 16);
        uint32_t lp = (uint32_t)__bfloat16_as_ushort(l0) | ((uint32_t)__bfloat16_as_ushort(l1) << 16);
        uint32_t off = (uint32_t)chunk * 16384u + (uint32_t)(row * 128) + (uint32_t)((kc * 2) ^ ((row & 7) << 4));
        *(uint32_t*)(s_mm + SM_XHI + off) = hp;
        *(uint32_t*)(s_mm + SM_XLO + off) = lp;
    }

    // ---- precomputed ldmatrix address pieces ----
    // A: row = wm*32 + mt*16 + (lane&15); kbyte = s*32 + ((lane>>4)<<4)
    int arow0 = wm * 32 + (lane & 15);
    uint32_t aoff0 = (uint32_t)(arow0 * 128);
    uint32_t aoff1 = aoff0 + 16 * 128;
    uint32_t kbA = (uint32_t)((lane >> 4) << 4);
    uint32_t swA = (uint32_t)((lane & 7) << 4);
    // B: row = wn*64 + p*16 + rB; kbyte = s*32 + (((lane>>3)&1)<<4)
    int rB = (lane & 7) + ((lane >> 4) << 3);
    uint32_t boffBase = (uint32_t)((wn * 64 + rB) * 128);
    uint32_t kbB = (uint32_t)(((lane >> 3) & 1) << 4);
    uint32_t swB = (uint32_t)((rB & 7) << 4);

    float acc[2][8][4];
    #pragma unroll
    for (int mt = 0; mt < 2; mt++)
        #pragma unroll
        for (int nt = 0; nt < 8; nt++)
            #pragma unroll
            for (int e = 0; e < 4; e++) acc[mt][nt][e] = 0.0f;

    uint4* dh = (uint4*)(s_mm + SM_WHI);
    uint4* dl = (uint4*)(s_mm + SM_WLO);

    for (int c = 0; c < 4; c++) {
        // stream W chunk (pre-swizzled) into smem
        const uint4* sh = g_Whi4 + c * 2048;
        const uint4* sl = g_Wlo4 + c * 2048;
        #pragma unroll
        for (int i = 0; i < 4; i++) {
            dh[tid + i * 512] = sh[tid + i * 512];
            dl[tid + i * 512] = sl[tid + i * 512];
        }
        __syncthreads();

        uint32_t xbaseH = smb + SM_XHI + c * 16384;
        uint32_t xbaseL = smb + SM_XLO + c * 16384;
        uint32_t wbaseH = smb + SM_WHI;
        uint32_t wbaseL = smb + SM_WLO;

        #pragma unroll
        for (int s = 0; s < 4; s++) {
            uint32_t ka = (uint32_t)(s * 32) + kbA;
            uint32_t koffA = ka ^ swA;
            uint32_t xh[2][4], xl[2][4];
            ldsm_x4(xh[0], xbaseH + aoff0 + koffA);
            ldsm_x4(xh[1], xbaseH + aoff1 + koffA);
            ldsm_x4(xl[0], xbaseL + aoff0 + koffA);
            ldsm_x4(xl[1], xbaseL + aoff1 + koffA);

            uint32_t kb = (uint32_t)(s * 32) + kbB;
            uint32_t koffB = kb ^ swB;
            #pragma unroll
            for (int p = 0; p < 4; p++) {
                uint32_t boff = boffBase + (uint32_t)(p * 16 * 128) + koffB;
                uint32_t wh[4], wl[4];
                ldsm_x4(wh, wbaseH + boff);
                ldsm_x4(wl, wbaseL + boff);
                #pragma unroll
                for (int mt = 0; mt < 2; mt++) {
                    mma_bf16(acc[mt][2*p],   xh[mt], &wh[0]);
                    mma_bf16(acc[mt][2*p],   xh[mt], &wl[0]);
                    mma_bf16(acc[mt][2*p],   xl[mt], &wh[0]);
                    mma_bf16(acc[mt][2*p+1], xh[mt], &wh[2]);
                    mma_bf16(acc[mt][2*p+1], xh[mt], &wl[2]);
                    mma_bf16(acc[mt][2*p+1], xl[mt], &wh[2]);
                }
            }
        }
        __syncthreads();
    }

    // ---- LayerNorm epilogue ----
    // lane holds: rows wm*32 + mt*16 + half*8 + (lane>>2);
    // cols wn*64 + nt*8 + (lane&3)*2 + q ; acc idx e = half*2 + q
    int colb = wn * 64 + (lane & 3) * 2;

    #pragma unroll
    for (int mt = 0; mt < 2; mt++) {
        #pragma unroll
        for (int half = 0; half < 2; half++) {
            float s1 = 0.f, s2 = 0.f;
            #pragma unroll
            for (int nt = 0; nt < 8; nt++) {
                int col0 = colb + nt * 8;
                float h0 = acc[mt][nt][half*2]     + biasS[col0];
                float h1 = acc[mt][nt][half*2 + 1] + biasS[col0 + 1];
                s1 += h0 + h1;
                s2 += h0 * h0 + h1 * h1;
            }
            s1 += __shfl_xor_sync(0xffffffffu, s1, 1);
            s2 += __shfl_xor_sync(0xffffffffu, s2, 1);
            s1 += __shfl_xor_sync(0xffffffffu, s1, 2);
            s2 += __shfl_xor_sync(0xffffffffu, s2, 2);
            if ((lane & 3) == 0) {
                int row = wm * 32 + mt * 16 + half * 8 + (lane >> 2);
                red2[wn * 128 + row] = make_float2(s1, s2);
            }
        }
    }
    __syncthreads();

    float gate = 1.0f / (1.0f + expf(-gate_logit[0]));

    #pragma unroll
    for (int mt = 0; mt < 2; mt++) {
        #pragma unroll
        for (int half = 0; half < 2; half++) {
            int row = wm * 32 + mt * 16 + half * 8 + (lane >> 2);
            float2 r0 = red2[0 * 128 + row];
            float2 r1 = red2[1 * 128 + row];
            float2 r2 = red2[2 * 128 + row];
            float2 r3 = red2[3 * 128 + row];
            float s1 = r0.x + r1.x + r2.x + r3.x;
            float s2 = r0.y + r1.y + r2.y + r3.y;
            float mu   = s1 * (1.0f / 256.0f);
            float var  = s2 * (1.0f / 256.0f) - mu * mu;
            float rstd = rsqrtf(var + 1e-5f);

            float* orow = out + ((size_t)bid * 128 + row) * C;
            #pragma unroll
            for (int nt = 0; nt < 8; nt++) {
                int col0 = colb + nt * 8;
                float h0 = acc[mt][nt][half*2]     + biasS[col0];
                float h1 = acc[mt][nt][half*2 + 1] + biasS[col0 + 1];
                float2 o;
                o.x = ((h0 - mu) * rstd * gamS[col0]     + betS[col0])     * gate;
                o.y = ((h1 - mu) * rstd * gamS[col0 + 1] + betS[col0 + 1]) * gate;
                *(float2*)(orow + col0) = o;
            }
        }
    }
}

// ============================================================================
// launch
// ============================================================================
extern "C" void kernel_launch(void* const* d_in, const int* in_sizes, int n_in,
                              void* d_out, int out_size)
{
    const float* query = (const float*)d_in[0];
    const float* summ  = (const float*)d_in[1];
    const float* templ = (const float*)d_in[2];
    const float* wproj = (const float*)d_in[3];
    const float* bproj = (const float*)d_in[4];
    const float* gamma = (const float*)d_in[5];
    const float* beta  = (const float*)d_in[6];
    const float* glog  = (const float*)d_in[7];
    float* out = (float*)d_out;

    const int SIMS_SMEM = (2 * 64 * SQ_STRIDE + 64) * sizeof(float);
    cudaFuncSetAttribute(sims_kernel, cudaFuncAttributeMaxDynamicSharedMemorySize, SIMS_SMEM);
    cudaFuncSetAttribute(fused_mma_kernel, cudaFuncAttributeMaxDynamicSharedMemorySize, SM_TOTAL);

    prep_kernel<<<1, 256>>>(query, glog, out);
    wprep_kernel<<<128, 256>>>(wproj);
    sims_kernel<<<NPAD / 64, 256, SIMS_SMEM>>>(summ);
    topk_part_kernel<<<B * 4, 256>>>();
    topk_merge_kernel<<<B, 32>>>();
    fused_mma_kernel<<<B * KTOP / 2, 512, SM_TOTAL>>>(templ, bproj, gamma, beta, glog, out);
}

// round 4
// speedup vs baseline: 1.7375x; 1.1588x over previous
#include <cuda_runtime.h>
#include <cuda_bf16.h>
#include <math.h>
#include <stdint.h>

#define B   64
#define C   256
#define N   20000
#define NPAD 20032          // 313 * 64
#define NT  64
#define KTOP 8
#define PAGE (NT*C)         // 16384 floats per template page
#define GATE_OFF (B*KTOP*NT*C)

// ---- device scratch ----
__device__ float g_qn[B*C];
__device__ float g_sims[B*NPAD];
__device__ int   g_topidx[B*KTOP];
__device__ unsigned long long g_cand_k[B*32];
__device__ uint4 g_Whi4[8192];   // 4 chunk-tiles of 256 rows x 64 bf16 (128B rows, XOR-swizzled)
__device__ uint4 g_Wlo4[8192];

#define SW128(b) ((b) ^ (((b) >> 3) & 0x70))

__device__ __forceinline__ uint32_t smem_u32(const void* p) {
    uint32_t a;
    asm("{ .reg .u64 t; cvta.to.shared.u64 t, %1; cvt.u32.u64 %0, t; }" : "=r"(a) : "l"(p));
    return a;
}

__device__ __forceinline__ void ldsm_x4(uint32_t* r, uint32_t addr) {
    asm volatile("ldmatrix.sync.aligned.m8n8.x4.shared.b16 {%0,%1,%2,%3}, [%4];"
                 : "=r"(r[0]), "=r"(r[1]), "=r"(r[2]), "=r"(r[3]) : "r"(addr));
}

__device__ __forceinline__ void mma_bf16(float* c, const uint32_t* a, const uint32_t* b) {
    asm volatile(
        "mma.sync.aligned.m16n8k16.row.col.f32.bf16.bf16.f32 "
        "{%0,%1,%2,%3}, {%4,%5,%6,%7}, {%8,%9}, {%0,%1,%2,%3};"
        : "+f"(c[0]), "+f"(c[1]), "+f"(c[2]), "+f"(c[3])
        : "r"(a[0]), "r"(a[1]), "r"(a[2]), "r"(a[3]), "r"(b[0]), "r"(b[1]));
}

// monotone key: bigger value -> bigger key; tie -> lower index bigger key
__device__ __forceinline__ unsigned long long mk_key(float f, int n) {
    int s = __float_as_int(f);
    unsigned u = (unsigned)s ^ (unsigned)((s >> 31) | 0x80000000);
    return ((unsigned long long)u << 32) | (unsigned)(0xffffffffu - (unsigned)n);
}

// ============================================================================
// Kernel 1: normalize queries; emit gate outputs
// ============================================================================
__global__ void prep_kernel(const float* __restrict__ q,
                            const float* __restrict__ gate_logit,
                            float* __restrict__ out)
{
    int tid = threadIdx.x, lane = tid & 31, w = tid >> 5;
    for (int r = w; r < B; r += 8) {
        const float4* qr = (const float4*)(q + r * C);
        float4 a = qr[lane*2], b = qr[lane*2 + 1];
        float ss = a.x*a.x + a.y*a.y + a.z*a.z + a.w*a.w
                 + b.x*b.x + b.y*b.y + b.z*b.z + b.w*b.w;
        #pragma unroll
        for (int o = 16; o > 0; o >>= 1) ss += __shfl_xor_sync(0xffffffffu, ss, o);
        float inv = 1.0f / fmaxf(sqrtf(ss), 1e-12f);
        float4* dst = (float4*)(g_qn + r * C);
        a.x*=inv; a.y*=inv; a.z*=inv; a.w*=inv;
        b.x*=inv; b.y*=inv; b.z*=inv; b.w*=inv;
        dst[lane*2] = a; dst[lane*2 + 1] = b;
    }
    if (tid < B) {
        float gate = 1.0f / (1.0f + expf(-gate_logit[0]));
        out[GATE_OFF + tid] = gate;
    }
}

// ============================================================================
// Kernel 1b: W -> bf16 hi/lo, chunk-tiled (k/64), 128B rows, XOR swizzle
// ============================================================================
__global__ void wprep_kernel(const float* __restrict__ wproj)
{
    int p = blockIdx.x * 256 + threadIdx.x;   // 32768 pairs
    int row = p >> 7, pp = p & 127;
    int k = pp * 2, chunk = pp >> 5, kc = k & 63;
    float2 v = *(const float2*)(wproj + row * C + k);
    __nv_bfloat16 h0 = __float2bfloat16(v.x), h1 = __float2bfloat16(v.y);
    float r0 = v.x - __bfloat162float(h0), r1 = v.y - __bfloat162float(h1);
    __nv_bfloat16 l0 = __float2bfloat16(r0), l1 = __float2bfloat16(r1);
    uint32_t hp = (uint32_t)__bfloat16_as_ushort(h0) | ((uint32_t)__bfloat16_as_ushort(h1) << 16);
    uint32_t lp = (uint32_t)__bfloat16_as_ushort(l0) | ((uint32_t)__bfloat16_as_ushort(l1) << 16);
    uint32_t off = (uint32_t)SW128(row * 128 + kc * 2);
    uint32_t idx = (uint32_t)chunk * 8192u + (off >> 2);
    ((uint32_t*)g_Whi4)[idx] = hp;
    ((uint32_t*)g_Wlo4)[idx] = lp;
}

// ============================================================================
// Kernel 2: sims = qn @ norm(summaries)^T
// ============================================================================
#define SQ_STRIDE 260
extern __shared__ float s_sims[];

__global__ __launch_bounds__(256) void sims_kernel(const float* __restrict__ summ)
{
    float* qs   = s_sims;
    float* ssm  = qs  + 64 * SQ_STRIDE;
    float* sinv = ssm + 64 * SQ_STRIDE;

    int tid = threadIdx.x;
    int n0  = blockIdx.x * 64;

    for (int i = tid; i < 64 * 64; i += 256) {
        int row = i >> 6, col = i & 63;
        float4 v = ((const float4*)g_qn)[row * 64 + col];
        *(float4*)(qs + row * SQ_STRIDE + col * 4) = v;
    }
    for (int i = tid; i < 64 * 64; i += 256) {
        int row = i >> 6, col = i & 63;
        int n = n0 + row;
        float4 v = make_float4(0.f, 0.f, 0.f, 0.f);
        if (n < N) v = ((const float4*)summ)[n * 64 + col];
        *(float4*)(ssm + row * SQ_STRIDE + col * 4) = v;
    }
    __syncthreads();

    int lane = tid & 31, w = tid >> 5;
    for (int r = w; r < 64; r += 8) {
        float4 a = *(float4*)(ssm + r * SQ_STRIDE + lane * 8);
        float4 b = *(float4*)(ssm + r * SQ_STRIDE + lane * 8 + 4);
        float ss = a.x*a.x + a.y*a.y + a.z*a.z + a.w*a.w
                 + b.x*b.x + b.y*b.y + b.z*b.z + b.w*b.w;
        #pragma unroll
        for (int o = 16; o > 0; o >>= 1) ss += __shfl_xor_sync(0xffffffffu, ss, o);
        if (lane == 0) sinv[r] = 1.0f / fmaxf(sqrtf(ss), 1e-12f);
    }
    __syncthreads();

    int tx = tid & 15, ty = tid >> 4;
    float acc[4][4];
    #pragma unroll
    for (int r = 0; r < 4; r++)
        #pragma unroll
        for (int c = 0; c < 4; c++) acc[r][c] = 0.0f;

    for (int kk = 0; kk < 256; kk += 4) {
        float4 qf[4];
        #pragma unroll
        for (int r = 0; r < 4; r++)
            qf[r] = *(float4*)(qs + (r * 16 + ty) * SQ_STRIDE + kk);
        #pragma unroll
        for (int c = 0; c < 4; c++) {
            float4 sf = *(float4*)(ssm + (c * 16 + tx) * SQ_STRIDE + kk);
            #pragma unroll
            for (int r = 0; r < 4; r++) {
                acc[r][c] += qf[r].x * sf.x;
                acc[r][c] += qf[r].y * sf.y;
                acc[r][c] += qf[r].z * sf.z;
                acc[r][c] += qf[r].w * sf.w;
            }
        }
    }

    #pragma unroll
    for (int r = 0; r < 4; r++) {
        int b = r * 16 + ty;
        #pragma unroll
        for (int c = 0; c < 4; c++) {
            int nl = c * 16 + tx;
            int n  = n0 + nl;
            float v = (n < N) ? acc[r][c] * sinv[nl] : -INFINITY;
            g_sims[b * NPAD + n] = v;
        }
    }
}

// ============================================================================
// Kernel 3a: partial top-8 per (query, quarter) — key-based, shuffle select
// grid = B*4, block = 256 (8 warps). Part length 5008 = 1252 float4.
// ============================================================================
__global__ __launch_bounds__(256) void topk_part_kernel()
{
    __shared__ unsigned long long wk[64];   // 8 warps x 8 winners

    int b = blockIdx.x >> 2, part = blockIdx.x & 3;
    int tid = threadIdx.x, lane = tid & 31, wid = tid >> 5;
    int nbase0 = part * 5008;
    const float4* rowp = (const float4*)(g_sims + (size_t)b * NPAD + nbase0);

    unsigned long long k[KTOP];
    #pragma unroll
    for (int j = 0; j < KTOP; j++) k[j] = 0ull;

    for (int i = tid; i < 1252; i += 256) {
        float4 v = rowp[i];
        int nb = nbase0 + i * 4;
        float vv[4] = {v.x, v.y, v.z, v.w};
        #pragma unroll
        for (int e = 0; e < 4; e++) {
            unsigned long long key = mk_key(vv[e], nb + e);
            if (key > k[KTOP-1]) {
                int p = KTOP - 1;
                #pragma unroll
                for (int j = KTOP - 1; j > 0; j--) {
                    if (key > k[j-1]) { k[j] = k[j-1]; p = j - 1; }
                    else break;
                }
                k[p] = key;
            }
        }
    }

    // per-warp: 8x (butterfly argmax + pop) — registers sorted desc, best = k[0]
    #pragma unroll
    for (int it = 0; it < KTOP; it++) {
        unsigned long long m = k[0];
        #pragma unroll
        for (int o = 16; o > 0; o >>= 1) {
            unsigned long long t = __shfl_xor_sync(0xffffffffu, m, o);
            if (t > m) m = t;
        }
        if (k[0] == m) {
            #pragma unroll
            for (int j = 0; j < KTOP - 1; j++) k[j] = k[j+1];
            k[KTOP-1] = 0ull;
        }
        if (lane == 0) wk[wid * 8 + it] = m;
    }
    __syncthreads();

    // warp 0 merges 64 candidates -> top 8 of this part
    if (wid == 0) {
        unsigned long long a = wk[lane], c = wk[lane + 32];
        #pragma unroll
        for (int it = 0; it < KTOP; it++) {
            unsigned long long m = (a > c) ? a : c;
            #pragma unroll
            for (int o = 16; o > 0; o >>= 1) {
                unsigned long long t = __shfl_xor_sync(0xffffffffu, m, o);
                if (t > m) m = t;
            }
            if (a == m) a = 0ull;
            else if (c == m) c = 0ull;
            if (lane == 0) g_cand_k[b * 32 + part * 8 + it] = m;
        }
    }
}

// ============================================================================
// Kernel 3b: merge 32 candidate keys -> ordered top-8 (one warp per query)
// ============================================================================
__global__ void topk_merge_kernel()
{
    int b = blockIdx.x, lane = threadIdx.x;
    unsigned long long key = g_cand_k[b * 32 + lane];

    #pragma unroll
    for (int sel = 0; sel < KTOP; sel++) {
        unsigned long long m = key;
        #pragma unroll
        for (int o = 16; o > 0; o >>= 1) {
            unsigned long long t = __shfl_xor_sync(0xffffffffu, m, o);
            if (t > m) m = t;
        }
        if (key == m) {
            g_topidx[b * KTOP + sel] = (int)(0xffffffffu - (unsigned)(m & 0xffffffffu));
            key = 0ull;
        }
    }
}

// ============================================================================
// Kernel 4: mma.sync fused  gather -> (x@W^T + b) -> LN -> gate -> out
// ============================================================================
#define SM_XHI   0              // 4 tiles x 16KB (128 rows x 128B)
#define SM_XLO   65536
#define SM_WHI   131072         // 256 rows x 128B = 32KB (current chunk)
#define SM_WLO   163840
#define SM_PAR   196608         // bias | gamma | beta (256 f32 each)
#define SM_RED   199680         // 4 x 128 float2
#define SM_TOTAL 203776

extern __shared__ char s_mm[];

__global__ __launch_bounds__(512, 1) void fused_mma_kernel(
    const float* __restrict__ templates,
    const float* __restrict__ bproj,
    const float* __restrict__ gamma_g,
    const float* __restrict__ beta_g,
    const float* __restrict__ gate_logit,
    float* __restrict__ out)
{
    uint32_t smb = smem_u32(s_mm);
    int tid = threadIdx.x, wid = tid >> 5, lane = tid & 31;
    int bid = blockIdx.x;
    int wm = wid & 3, wn = wid >> 2;

    float* biasS = (float*)(s_mm + SM_PAR);
    float* gamS  = biasS + 256;
    float* betS  = gamS + 256;
    float2* red2 = (float2*)(s_mm + SM_RED);   // [4][128]
    if (tid < 256) { biasS[tid] = bproj[tid]; gamS[tid] = gamma_g[tid]; betS[tid] = beta_g[tid]; }

    // ---- gather + convert x (2 pages = 128 rows x 256 k) into hi/lo tiles ----
    int p0 = g_topidx[2*bid], p1 = g_topidx[2*bid + 1];
    for (int i = tid; i < 16384; i += 512) {            // bf16 pairs
        int row = i >> 7, pp = i & 127;
        int k = pp * 2, chunk = pp >> 5, kc = k & 63;
        const float* src = templates + (size_t)(row < 64 ? p0 : p1) * PAGE + (row & 63) * C + k;
        float2 v = *(const float2*)src;
        __nv_bfloat16 h0 = __float2bfloat16(v.x), h1 = __float2bfloat16(v.y);
        float r0 = v.x - __bfloat162float(h0), r1 = v.y - __bfloat162float(h1);
        __nv_bfloat16 l0 = __float2bfloat16(r0), l1 = __float2bfloat16(r1);
        uint32_t hp = (uint32_t)__bfloat16_as_ushort(h0) | ((uint32_t)__bfloat16_as_ushort(h1) << 16);
        uint32_t lp = (uint32_t)__bfloat16_as_ushort(l0) | ((uint32_t)__bfloat16_as_ushort(l1) << 16);
        uint32_t off = (uint32_t)chunk * 16384u + (uint32_t)(row * 128) + (uint32_t)((kc * 2) ^ ((row & 7) << 4));
        *(uint32_t*)(s_mm + SM_XHI + off) = hp;
        *(uint32_t*)(s_mm + SM_XLO + off) = lp;
    }

    // ---- precomputed ldmatrix address pieces ----
    int arow0 = wm * 32 + (lane & 15);
    uint32_t aoff0 = (uint32_t)(arow0 * 128);
    uint32_t aoff1 = aoff0 + 16 * 128;
    uint32_t kbA = (uint32_t)((lane >> 4) << 4);
    uint32_t swA = (uint32_t)((lane & 7) << 4);
    int rB = (lane & 7) + ((lane >> 4) << 3);
    uint32_t boffBase = (uint32_t)((wn * 64 + rB) * 128);
    uint32_t kbB = (uint32_t)(((lane >> 3) & 1) << 4);
    uint32_t swB = (uint32_t)((rB & 7) << 4);

    float acc[2][8][4];
    #pragma unroll
    for (int mt = 0; mt < 2; mt++)
        #pragma unroll
        for (int nt = 0; nt < 8; nt++)
            #pragma unroll
            for (int e = 0; e < 4; e++) acc[mt][nt][e] = 0.0f;

    uint4* dh = (uint4*)(s_mm + SM_WHI);
    uint4* dl = (uint4*)(s_mm + SM_WLO);

    for (int c = 0; c < 4; c++) {
        const uint4* sh = g_Whi4 + c * 2048;
        const uint4* sl = g_Wlo4 + c * 2048;
        #pragma unroll
        for (int i = 0; i < 4; i++) {
            dh[tid + i * 512] = sh[tid + i * 512];
            dl[tid + i * 512] = sl[tid + i * 512];
        }
        __syncthreads();

        uint32_t xbaseH = smb + SM_XHI + c * 16384;
        uint32_t xbaseL = smb + SM_XLO + c * 16384;
        uint32_t wbaseH = smb + SM_WHI;
        uint32_t wbaseL = smb + SM_WLO;

        #pragma unroll
        for (int s = 0; s < 4; s++) {
            uint32_t ka = (uint32_t)(s * 32) + kbA;
            uint32_t koffA = ka ^ swA;
            uint32_t xh[2][4], xl[2][4];
            ldsm_x4(xh[0], xbaseH + aoff0 + koffA);
            ldsm_x4(xh[1], xbaseH + aoff1 + koffA);
            ldsm_x4(xl[0], xbaseL + aoff0 + koffA);
            ldsm_x4(xl[1], xbaseL + aoff1 + koffA);

            uint32_t kb = (uint32_t)(s * 32) + kbB;
            uint32_t koffB = kb ^ swB;
            #pragma unroll
            for (int p = 0; p < 4; p++) {
                uint32_t boff = boffBase + (uint32_t)(p * 16 * 128) + koffB;
                uint32_t wh[4], wl[4];
                ldsm_x4(wh, wbaseH + boff);
                ldsm_x4(wl, wbaseL + boff);
                #pragma unroll
                for (int mt = 0; mt < 2; mt++) {
                    mma_bf16(acc[mt][2*p],   xh[mt], &wh[0]);
                    mma_bf16(acc[mt][2*p],   xh[mt], &wl[0]);
                    mma_bf16(acc[mt][2*p],   xl[mt], &wh[0]);
                    mma_bf16(acc[mt][2*p+1], xh[mt], &wh[2]);
                    mma_bf16(acc[mt][2*p+1], xh[mt], &wl[2]);
                    mma_bf16(acc[mt][2*p+1], xl[mt], &wh[2]);
                }
            }
        }
        __syncthreads();
    }

    // ---- LayerNorm epilogue ----
    int colb = wn * 64 + (lane & 3) * 2;

    #pragma unroll
    for (int mt = 0; mt < 2; mt++) {
        #pragma unroll
        for (int half = 0; half < 2; half++) {
            float s1 = 0.f, s2 = 0.f;
            #pragma unroll
            for (int nt = 0; nt < 8; nt++) {
                int col0 = colb + nt * 8;
                float h0 = acc[mt][nt][half*2]     + biasS[col0];
                float h1 = acc[mt][nt][half*2 + 1] + biasS[col0 + 1];
                s1 += h0 + h1;
                s2 += h0 * h0 + h1 * h1;
            }
            s1 += __shfl_xor_sync(0xffffffffu, s1, 1);
            s2 += __shfl_xor_sync(0xffffffffu, s2, 1);
            s1 += __shfl_xor_sync(0xffffffffu, s1, 2);
            s2 += __shfl_xor_sync(0xffffffffu, s2, 2);
            if ((lane & 3) == 0) {
                int row = wm * 32 + mt * 16 + half * 8 + (lane >> 2);
                red2[wn * 128 + row] = make_float2(s1, s2);
            }
        }
    }
    __syncthreads();

    float gate = 1.0f / (1.0f + expf(-gate_logit[0]));

    #pragma unroll
    for (int mt = 0; mt < 2; mt++) {
        #pragma unroll
        for (int half = 0; half < 2; half++) {
            int row = wm * 32 + mt * 16 + half * 8 + (lane >> 2);
            float2 r0 = red2[0 * 128 + row];
            float2 r1 = red2[1 * 128 + row];
            float2 r2 = red2[2 * 128 + row];
            float2 r3 = red2[3 * 128 + row];
            float s1 = r0.x + r1.x + r2.x + r3.x;
            float s2 = r0.y + r1.y + r2.y + r3.y;
            float mu   = s1 * (1.0f / 256.0f);
            float var  = s2 * (1.0f / 256.0f) - mu * mu;
            float rstd = rsqrtf(var + 1e-5f);

            float* orow = out + ((size_t)bid * 128 + row) * C;
            #pragma unroll
            for (int nt = 0; nt < 8; nt++) {
                int col0 = colb + nt * 8;
                float h0 = acc[mt][nt][half*2]     + biasS[col0];
                float h1 = acc[mt][nt][half*2 + 1] + biasS[col0 + 1];
                float2 o;
                o.x = ((h0 - mu) * rstd * gamS[col0]     + betS[col0])     * gate;
                o.y = ((h1 - mu) * rstd * gamS[col0 + 1] + betS[col0 + 1]) * gate;
                *(float2*)(orow + col0) = o;
            }
        }
    }
}

// ============================================================================
// launch
// ============================================================================
extern "C" void kernel_launch(void* const* d_in, const int* in_sizes, int n_in,
                              void* d_out, int out_size)
{
    const float* query = (const float*)d_in[0];
    const float* summ  = (const float*)d_in[1];
    const float* templ = (const float*)d_in[2];
    const float* wproj = (const float*)d_in[3];
    const float* bproj = (const float*)d_in[4];
    const float* gamma = (const float*)d_in[5];
    const float* beta  = (const float*)d_in[6];
    const float* glog  = (const float*)d_in[7];
    float* out = (float*)d_out;

    const int SIMS_SMEM = (2 * 64 * SQ_STRIDE + 64) * sizeof(float);
    cudaFuncSetAttribute(sims_kernel, cudaFuncAttributeMaxDynamicSharedMemorySize, SIMS_SMEM);
    cudaFuncSetAttribute(fused_mma_kernel, cudaFuncAttributeMaxDynamicSharedMemorySize, SM_TOTAL);

    prep_kernel<<<1, 256>>>(query, glog, out);
    wprep_kernel<<<128, 256>>>(wproj);
    sims_kernel<<<NPAD / 64, 256, SIMS_SMEM>>>(summ);
    topk_part_kernel<<<B * 4, 256>>>();
    topk_merge_kernel<<<B, 32>>>();
    fused_mma_kernel<<<B * KTOP / 2, 512, SM_TOTAL>>>(templ, bproj, gamma, beta, glog, out);
}

// round 5
// speedup vs baseline: 1.7866x; 1.0282x over previous
#include <cuda_runtime.h>
#include <cuda_bf16.h>
#include <math.h>
#include <stdint.h>

#define B   64
#define C   256
#define N   20000
#define NPAD 20032          // 313 * 64
#define NT  64
#define KTOP 8
#define PAGE (NT*C)         // 16384 floats per template page
#define GATE_OFF (B*KTOP*NT*C)
#define PARTS 8
#define PARTF 2504          // NPAD / PARTS floats
#define PART4 626           // PARTF / 4

// ---- device scratch ----
__device__ float g_qn[B*C];
__device__ float g_sims[B*NPAD];
__device__ int   g_topidx[B*KTOP];
__device__ unsigned long long g_cand_k[B*64];
__device__ uint4 g_Whi4[8192];   // 4 chunk-tiles of 256 rows x 64 bf16 (128B rows, XOR-swizzled)
__device__ uint4 g_Wlo4[8192];

#define SW128(b) ((b) ^ (((b) >> 3) & 0x70))

__device__ __forceinline__ uint32_t smem_u32(const void* p) {
    uint32_t a;
    asm("{ .reg .u64 t; cvta.to.shared.u64 t, %1; cvt.u32.u64 %0, t; }" : "=r"(a) : "l"(p));
    return a;
}

__device__ __forceinline__ void ldsm_x4(uint32_t* r, uint32_t addr) {
    asm volatile("ldmatrix.sync.aligned.m8n8.x4.shared.b16 {%0,%1,%2,%3}, [%4];"
                 : "=r"(r[0]), "=r"(r[1]), "=r"(r[2]), "=r"(r[3]) : "r"(addr));
}

__device__ __forceinline__ void mma_bf16(float* c, const uint32_t* a, const uint32_t* b) {
    asm volatile(
        "mma.sync.aligned.m16n8k16.row.col.f32.bf16.bf16.f32 "
        "{%0,%1,%2,%3}, {%4,%5,%6,%7}, {%8,%9}, {%0,%1,%2,%3};"
        : "+f"(c[0]), "+f"(c[1]), "+f"(c[2]), "+f"(c[3])
        : "r"(a[0]), "r"(a[1]), "r"(a[2]), "r"(a[3]), "r"(b[0]), "r"(b[1]));
}

// monotone key: bigger value -> bigger key; tie -> lower index bigger key
__device__ __forceinline__ unsigned long long mk_key(float f, int n) {
    int s = __float_as_int(f);
    unsigned u = (unsigned)s ^ (unsigned)((s >> 31) | 0x80000000);
    return ((unsigned long long)u << 32) | (unsigned)(0xffffffffu - (unsigned)n);
}

// ============================================================================
// Kernel 1: W -> bf16 hi/lo pre-swizzled tiles (blocks 0-127)
//           + query normalize + gate outputs (block 128)
// ============================================================================
__global__ void prep_all_kernel(const float* __restrict__ wproj,
                                const float* __restrict__ q,
                                const float* __restrict__ gate_logit,
                                float* __restrict__ out)
{
    int tid = threadIdx.x;
    if (blockIdx.x < 128) {
        int p = blockIdx.x * 256 + tid;   // 32768 pairs
        int row = p >> 7, pp = p & 127;
        int k = pp * 2, chunk = pp >> 5, kc = k & 63;
        float2 v = *(const float2*)(wproj + row * C + k);
        __nv_bfloat16 h0 = __float2bfloat16(v.x), h1 = __float2bfloat16(v.y);
        float r0 = v.x - __bfloat162float(h0), r1 = v.y - __bfloat162float(h1);
        __nv_bfloat16 l0 = __float2bfloat16(r0), l1 = __float2bfloat16(r1);
        uint32_t hp = (uint32_t)__bfloat16_as_ushort(h0) | ((uint32_t)__bfloat16_as_ushort(h1) << 16);
        uint32_t lp = (uint32_t)__bfloat16_as_ushort(l0) | ((uint32_t)__bfloat16_as_ushort(l1) << 16);
        uint32_t off = (uint32_t)SW128(row * 128 + kc * 2);
        uint32_t idx = (uint32_t)chunk * 8192u + (off >> 2);
        ((uint32_t*)g_Whi4)[idx] = hp;
        ((uint32_t*)g_Wlo4)[idx] = lp;
    } else {
        int lane = tid & 31, w = tid >> 5;
        for (int r = w; r < B; r += 8) {
            const float4* qr = (const float4*)(q + r * C);
            float4 a = qr[lane*2], b = qr[lane*2 + 1];
            float ss = a.x*a.x + a.y*a.y + a.z*a.z + a.w*a.w
                     + b.x*b.x + b.y*b.y + b.z*b.z + b.w*b.w;
            #pragma unroll
            for (int o = 16; o > 0; o >>= 1) ss += __shfl_xor_sync(0xffffffffu, ss, o);
            float inv = 1.0f / fmaxf(sqrtf(ss), 1e-12f);
            float4* dst = (float4*)(g_qn + r * C);
            a.x*=inv; a.y*=inv; a.z*=inv; a.w*=inv;
            b.x*=inv; b.y*=inv; b.z*=inv; b.w*=inv;
            dst[lane*2] = a; dst[lane*2 + 1] = b;
        }
        if (tid < B) {
            float gate = 1.0f / (1.0f + expf(-gate_logit[0]));
            out[GATE_OFF + tid] = gate;
        }
    }
}

// ============================================================================
// Kernel 2: sims = qn @ norm(summaries)^T
// ============================================================================
#define SQ_STRIDE 260
extern __shared__ float s_sims[];

__global__ __launch_bounds__(256) void sims_kernel(const float* __restrict__ summ)
{
    float* qs   = s_sims;
    float* ssm  = qs  + 64 * SQ_STRIDE;
    float* sinv = ssm + 64 * SQ_STRIDE;

    int tid = threadIdx.x;
    int n0  = blockIdx.x * 64;

    for (int i = tid; i < 64 * 64; i += 256) {
        int row = i >> 6, col = i & 63;
        float4 v = ((const float4*)g_qn)[row * 64 + col];
        *(float4*)(qs + row * SQ_STRIDE + col * 4) = v;
    }
    for (int i = tid; i < 64 * 64; i += 256) {
        int row = i >> 6, col = i & 63;
        int n = n0 + row;
        float4 v = make_float4(0.f, 0.f, 0.f, 0.f);
        if (n < N) v = ((const float4*)summ)[n * 64 + col];
        *(float4*)(ssm + row * SQ_STRIDE + col * 4) = v;
    }
    __syncthreads();

    int lane = tid & 31, w = tid >> 5;
    for (int r = w; r < 64; r += 8) {
        float4 a = *(float4*)(ssm + r * SQ_STRIDE + lane * 8);
        float4 b = *(float4*)(ssm + r * SQ_STRIDE + lane * 8 + 4);
        float ss = a.x*a.x + a.y*a.y + a.z*a.z + a.w*a.w
                 + b.x*b.x + b.y*b.y + b.z*b.z + b.w*b.w;
        #pragma unroll
        for (int o = 16; o > 0; o >>= 1) ss += __shfl_xor_sync(0xffffffffu, ss, o);
        if (lane == 0) sinv[r] = 1.0f / fmaxf(sqrtf(ss), 1e-12f);
    }
    __syncthreads();

    int tx = tid & 15, ty = tid >> 4;
    float acc[4][4];
    #pragma unroll
    for (int r = 0; r < 4; r++)
        #pragma unroll
        for (int c = 0; c < 4; c++) acc[r][c] = 0.0f;

    for (int kk = 0; kk < 256; kk += 4) {
        float4 qf[4];
        #pragma unroll
        for (int r = 0; r < 4; r++)
            qf[r] = *(float4*)(qs + (r * 16 + ty) * SQ_STRIDE + kk);
        #pragma unroll
        for (int c = 0; c < 4; c++) {
            float4 sf = *(float4*)(ssm + (c * 16 + tx) * SQ_STRIDE + kk);
            #pragma unroll
            for (int r = 0; r < 4; r++) {
                acc[r][c] += qf[r].x * sf.x;
                acc[r][c] += qf[r].y * sf.y;
                acc[r][c] += qf[r].z * sf.z;
                acc[r][c] += qf[r].w * sf.w;
            }
        }
    }

    #pragma unroll
    for (int r = 0; r < 4; r++) {
        int b = r * 16 + ty;
        #pragma unroll
        for (int c = 0; c < 4; c++) {
            int nl = c * 16 + tx;
            int n  = n0 + nl;
            float v = (n < N) ? acc[r][c] * sinv[nl] : -INFINITY;
            g_sims[b * NPAD + n] = v;
        }
    }
}

// ============================================================================
// Kernel 3a: partial top-8 per (query, eighth) — prefetched, shuffle select
// grid = B*8, block = 128 (4 warps). Part length 2504 = 626 float4.
// ============================================================================
__global__ __launch_bounds__(128) void topk_part_kernel()
{
    __shared__ unsigned long long wk[32];   // 4 warps x 8 winners

    int b = blockIdx.x >> 3, part = blockIdx.x & 7;
    int tid = threadIdx.x, lane = tid & 31, wid = tid >> 5;
    int nbase0 = part * PARTF;
    const float4* rowp = (const float4*)(g_sims + (size_t)b * NPAD + nbase0);

    // prefetch all 5 float4 (clamp last)
    float4 v[5];
    #pragma unroll
    for (int j = 0; j < 5; j++) {
        int idx = tid + j * 128;
        v[j] = rowp[idx < PART4 ? idx : PART4 - 1];
    }

    unsigned long long k[KTOP];
    #pragma unroll
    for (int j = 0; j < KTOP; j++) k[j] = 0ull;

    #pragma unroll
    for (int j = 0; j < 5; j++) {
        int idx = tid + j * 128;
        if (idx < PART4) {
            int nb = nbase0 + idx * 4;
            float vv[4] = {v[j].x, v[j].y, v[j].z, v[j].w};
            #pragma unroll
            for (int e = 0; e < 4; e++) {
                unsigned long long key = mk_key(vv[e], nb + e);
                if (key > k[KTOP-1]) {
                    int p = KTOP - 1;
                    #pragma unroll
                    for (int jj = KTOP - 1; jj > 0; jj--) {
                        if (key > k[jj-1]) { k[jj] = k[jj-1]; p = jj - 1; }
                        else break;
                    }
                    k[p] = key;
                }
            }
        }
    }

    // per-warp: 8x (butterfly argmax + pop)
    #pragma unroll
    for (int it = 0; it < KTOP; it++) {
        unsigned long long m = k[0];
        #pragma unroll
        for (int o = 16; o > 0; o >>= 1) {
            unsigned long long t = __shfl_xor_sync(0xffffffffu, m, o);
            if (t > m) m = t;
        }
        if (k[0] == m) {
            #pragma unroll
            for (int j = 0; j < KTOP - 1; j++) k[j] = k[j+1];
            k[KTOP-1] = 0ull;
        }
        if (lane == 0) wk[wid * 8 + it] = m;
    }
    __syncthreads();

    // warp 0 merges 32 candidates -> top 8 of this part
    if (wid == 0) {
        unsigned long long a = wk[lane];
        #pragma unroll
        for (int it = 0; it < KTOP; it++) {
            unsigned long long m = a;
            #pragma unroll
            for (int o = 16; o > 0; o >>= 1) {
                unsigned long long t = __shfl_xor_sync(0xffffffffu, m, o);
                if (t > m) m = t;
            }
            if (a == m) a = 0ull;
            if (lane == 0) g_cand_k[b * 64 + part * 8 + it] = m;
        }
    }
}

// ============================================================================
// Kernel 3b: merge 64 candidate keys -> ordered top-8 (one warp per query)
// ============================================================================
__global__ void topk_merge_kernel()
{
    int b = blockIdx.x, lane = threadIdx.x;
    unsigned long long a = g_cand_k[b * 64 + lane];
    unsigned long long c = g_cand_k[b * 64 + lane + 32];

    #pragma unroll
    for (int sel = 0; sel < KTOP; sel++) {
        unsigned long long m = (a > c) ? a : c;
        #pragma unroll
        for (int o = 16; o > 0; o >>= 1) {
            unsigned long long t = __shfl_xor_sync(0xffffffffu, m, o);
            if (t > m) m = t;
        }
        if (a == m) a = 0ull;
        else if (c == m) c = 0ull;
        if (lane == 0)
            g_topidx[b * KTOP + sel] = (int)(0xffffffffu - (unsigned)(m & 0xffffffffu));
    }
}

// ============================================================================
// Kernel 4: mma.sync fused  gather -> (x@W^T + b) -> LN -> gate -> out
// ============================================================================
#define SM_XHI   0              // 4 tiles x 16KB (128 rows x 128B)
#define SM_XLO   65536
#define SM_WHI   131072         // 256 rows x 128B = 32KB (current chunk)
#define SM_WLO   163840
#define SM_PAR   196608         // bias | gamma | beta (256 f32 each)
#define SM_RED   199680         // 4 x 128 float2
#define SM_TOTAL 203776

extern __shared__ char s_mm[];

__global__ __launch_bounds__(512, 1) void fused_mma_kernel(
    const float* __restrict__ templates,
    const float* __restrict__ bproj,
    const float* __restrict__ gamma_g,
    const float* __restrict__ beta_g,
    const float* __restrict__ gate_logit,
    float* __restrict__ out)
{
    uint32_t smb = smem_u32(s_mm);
    int tid = threadIdx.x, wid = tid >> 5, lane = tid & 31;
    int bid = blockIdx.x;
    int wm = wid & 3, wn = wid >> 2;

    float* biasS = (float*)(s_mm + SM_PAR);
    float* gamS  = biasS + 256;
    float* betS  = gamS + 256;
    float2* red2 = (float2*)(s_mm + SM_RED);   // [4][128]
    if (tid < 256) { biasS[tid] = bproj[tid]; gamS[tid] = gamma_g[tid]; betS[tid] = beta_g[tid]; }

    // ---- gather + convert x (2 pages = 128 rows x 256 k) into hi/lo tiles ----
    int p0 = g_topidx[2*bid], p1 = g_topidx[2*bid + 1];
    for (int i = tid; i < 16384; i += 512) {            // bf16 pairs
        int row = i >> 7, pp = i & 127;
        int k = pp * 2, chunk = pp >> 5, kc = k & 63;
        const float* src = templates + (size_t)(row < 64 ? p0 : p1) * PAGE + (row & 63) * C + k;
        float2 v = *(const float2*)src;
        __nv_bfloat16 h0 = __float2bfloat16(v.x), h1 = __float2bfloat16(v.y);
        float r0 = v.x - __bfloat162float(h0), r1 = v.y - __bfloat162float(h1);
        __nv_bfloat16 l0 = __float2bfloat16(r0), l1 = __float2bfloat16(r1);
        uint32_t hp = (uint32_t)__bfloat16_as_ushort(h0) | ((uint32_t)__bfloat16_as_ushort(h1) << 16);
        uint32_t lp = (uint32_t)__bfloat16_as_ushort(l0) | ((uint32_t)__bfloat16_as_ushort(l1) << 16);
        uint32_t off = (uint32_t)chunk * 16384u + (uint32_t)(row * 128) + (uint32_t)((kc * 2) ^ ((row & 7) << 4));
        *(uint32_t*)(s_mm + SM_XHI + off) = hp;
        *(uint32_t*)(s_mm + SM_XLO + off) = lp;
    }

    // ---- precomputed ldmatrix address pieces ----
    int arow0 = wm * 32 + (lane & 15);
    uint32_t aoff0 = (uint32_t)(arow0 * 128);
    uint32_t aoff1 = aoff0 + 16 * 128;
    uint32_t kbA = (uint32_t)((lane >> 4) << 4);
    uint32_t swA = (uint32_t)((lane & 7) << 4);
    int rB = (lane & 7) + ((lane >> 4) << 3);
    uint32_t boffBase = (uint32_t)((wn * 64 + rB) * 128);
    uint32_t kbB = (uint32_t)(((lane >> 3) & 1) << 4);
    uint32_t swB = (uint32_t)((rB & 7) << 4);

    float acc[2][8][4];
    #pragma unroll
    for (int mt = 0; mt < 2; mt++)
        #pragma unroll
        for (int nt = 0; nt < 8; nt++)
            #pragma unroll
            for (int e = 0; e < 4; e++) acc[mt][nt][e] = 0.0f;

    uint4* dh = (uint4*)(s_mm + SM_WHI);
    uint4* dl = (uint4*)(s_mm + SM_WLO);

    for (int c = 0; c < 4; c++) {
        const uint4* sh = g_Whi4 + c * 2048;
        const uint4* sl = g_Wlo4 + c * 2048;
        #pragma unroll
        for (int i = 0; i < 4; i++) {
            dh[tid + i * 512] = sh[tid + i * 512];
            dl[tid + i * 512] = sl[tid + i * 512];
        }
        __syncthreads();

        uint32_t xbaseH = smb + SM_XHI + c * 16384;
        uint32_t xbaseL = smb + SM_XLO + c * 16384;
        uint32_t wbaseH = smb + SM_WHI;
        uint32_t wbaseL = smb + SM_WLO;

        #pragma unroll
        for (int s = 0; s < 4; s++) {
            uint32_t ka = (uint32_t)(s * 32) + kbA;
            uint32_t koffA = ka ^ swA;
            uint32_t xh[2][4], xl[2][4];
            ldsm_x4(xh[0], xbaseH + aoff0 + koffA);
            ldsm_x4(xh[1], xbaseH + aoff1 + koffA);
            ldsm_x4(xl[0], xbaseL + aoff0 + koffA);
            ldsm_x4(xl[1], xbaseL + aoff1 + koffA);

            uint32_t kb = (uint32_t)(s * 32) + kbB;
            uint32_t koffB = kb ^ swB;
            #pragma unroll
            for (int p = 0; p < 4; p++) {
                uint32_t boff = boffBase + (uint32_t)(p * 16 * 128) + koffB;
                uint32_t wh[4], wl[4];
                ldsm_x4(wh, wbaseH + boff);
                ldsm_x4(wl, wbaseL + boff);
                #pragma unroll
                for (int mt = 0; mt < 2; mt++) {
                    mma_bf16(acc[mt][2*p],   xh[mt], &wh[0]);
                    mma_bf16(acc[mt][2*p],   xh[mt], &wl[0]);
                    mma_bf16(acc[mt][2*p],   xl[mt], &wh[0]);
                    mma_bf16(acc[mt][2*p+1], xh[mt], &wh[2]);
                    mma_bf16(acc[mt][2*p+1], xh[mt], &wl[2]);
                    mma_bf16(acc[mt][2*p+1], xl[mt], &wh[2]);
                }
            }
        }
        __syncthreads();
    }

    // ---- LayerNorm epilogue ----
    int colb = wn * 64 + (lane & 3) * 2;

    #pragma unroll
    for (int mt = 0; mt < 2; mt++) {
        #pragma unroll
        for (int half = 0; half < 2; half++) {
            float s1 = 0.f, s2 = 0.f;
            #pragma unroll
            for (int nt = 0; nt < 8; nt++) {
                int col0 = colb + nt * 8;
                float h0 = acc[mt][nt][half*2]     + biasS[col0];
                float h1 = acc[mt][nt][half*2 + 1] + biasS[col0 + 1];
                s1 += h0 + h1;
                s2 += h0 * h0 + h1 * h1;
            }
            s1 += __shfl_xor_sync(0xffffffffu, s1, 1);
            s2 += __shfl_xor_sync(0xffffffffu, s2, 1);
            s1 += __shfl_xor_sync(0xffffffffu, s1, 2);
            s2 += __shfl_xor_sync(0xffffffffu, s2, 2);
            if ((lane & 3) == 0) {
                int row = wm * 32 + mt * 16 + half * 8 + (lane >> 2);
                red2[wn * 128 + row] = make_float2(s1, s2);
            }
        }
    }
    __syncthreads();

    float gate = 1.0f / (1.0f + expf(-gate_logit[0]));

    #pragma unroll
    for (int mt = 0; mt < 2; mt++) {
        #pragma unroll
        for (int half = 0; half < 2; half++) {
            int row = wm * 32 + mt * 16 + half * 8 + (lane >> 2);
            float2 r0 = red2[0 * 128 + row];
            float2 r1 = red2[1 * 128 + row];
            float2 r2 = red2[2 * 128 + row];
            float2 r3 = red2[3 * 128 + row];
            float s1 = r0.x + r1.x + r2.x + r3.x;
            float s2 = r0.y + r1.y + r2.y + r3.y;
            float mu   = s1 * (1.0f / 256.0f);
            float var  = s2 * (1.0f / 256.0f) - mu * mu;
            float rstd = rsqrtf(var + 1e-5f);

            float* orow = out + ((size_t)bid * 128 + row) * C;
            #pragma unroll
            for (int nt = 0; nt < 8; nt++) {
                int col0 = colb + nt * 8;
                float h0 = acc[mt][nt][half*2]     + biasS[col0];
                float h1 = acc[mt][nt][half*2 + 1] + biasS[col0 + 1];
                float2 o;
                o.x = ((h0 - mu) * rstd * gamS[col0]     + betS[col0])     * gate;
                o.y = ((h1 - mu) * rstd * gamS[col0 + 1] + betS[col0 + 1]) * gate;
                *(float2*)(orow + col0) = o;
            }
        }
    }
}

// ============================================================================
// launch
// ============================================================================
extern "C" void kernel_launch(void* const* d_in, const int* in_sizes, int n_in,
                              void* d_out, int out_size)
{
    const float* query = (const float*)d_in[0];
    const float* summ  = (const float*)d_in[1];
    const float* templ = (const float*)d_in[2];
    const float* wproj = (const float*)d_in[3];
    const float* bproj = (const float*)d_in[4];
    const float* gamma = (const float*)d_in[5];
    const float* beta  = (const float*)d_in[6];
    const float* glog  = (const float*)d_in[7];
    float* out = (float*)d_out;

    const int SIMS_SMEM = (2 * 64 * SQ_STRIDE + 64) * sizeof(float);
    cudaFuncSetAttribute(sims_kernel, cudaFuncAttributeMaxDynamicSharedMemorySize, SIMS_SMEM);
    cudaFuncSetAttribute(fused_mma_kernel, cudaFuncAttributeMaxDynamicSharedMemorySize, SM_TOTAL);

    prep_all_kernel<<<129, 256>>>(wproj, query, glog, out);
    sims_kernel<<<NPAD / 64, 256, SIMS_SMEM>>>(summ);
    topk_part_kernel<<<B * PARTS, 128>>>();
    topk_merge_kernel<<<B, 32>>>();
    fused_mma_kernel<<<B * KTOP / 2, 512, SM_TOTAL>>>(templ, bproj, gamma, beta, glog, out);
}

// round 8
// speedup vs baseline: 2.4045x; 1.3459x over previous
#include <cuda_runtime.h>
#include <cuda_bf16.h>
#include <math.h>
#include <stdint.h>

#define B   64
#define C   256
#define N   20000
#define NPAD 20032          // 313 * 64
#define NT  64
#define KTOP 8
#define PAGE (NT*C)         // 16384 floats per template page
#define GATE_OFF (B*KTOP*NT*C)
#define PARTS 8
#define PARTF 2504          // NPAD / PARTS floats
#define PART4 626           // PARTF / 4

// ---- device scratch ----
__device__ float g_sims[B*NPAD];
__device__ unsigned long long g_cand_k[B*64];
__device__ uint4 g_Whi4[8192];   // 4 chunk-tiles of 256 rows x 64 bf16 (128B rows, XOR-swizzled)
__device__ uint4 g_Wlo4[8192];
__device__ uint32_t g_qhi[8192]; // 4 chunk-tiles of 64 rows x 64 bf16 (normalized q, swizzled) = 32KB
__device__ uint32_t g_qlo[8192];

#define SW128(b) ((b) ^ (((b) >> 3) & 0x70))

__device__ __forceinline__ uint32_t smem_u32(const void* p) {
    uint32_t a;
    asm("{ .reg .u64 t; cvta.to.shared.u64 t, %1; cvt.u32.u64 %0, t; }" : "=r"(a) : "l"(p));
    return a;
}

__device__ __forceinline__ void ldsm_x4(uint32_t* r, uint32_t addr) {
    asm volatile("ldmatrix.sync.aligned.m8n8.x4.shared.b16 {%0,%1,%2,%3}, [%4];"
                 : "=r"(r[0]), "=r"(r[1]), "=r"(r[2]), "=r"(r[3]) : "r"(addr));
}

__device__ __forceinline__ void mma_bf16(float* c, const uint32_t* a, const uint32_t* b) {
    asm volatile(
        "mma.sync.aligned.m16n8k16.row.col.f32.bf16.bf16.f32 "
        "{%0,%1,%2,%3}, {%4,%5,%6,%7}, {%8,%9}, {%0,%1,%2,%3};"
        : "+f"(c[0]), "+f"(c[1]), "+f"(c[2]), "+f"(c[3])
        : "r"(a[0]), "r"(a[1]), "r"(a[2]), "r"(a[3]), "r"(b[0]), "r"(b[1]));
}

// monotone key: bigger value -> bigger key; tie -> lower index bigger key
__device__ __forceinline__ unsigned long long mk_key(float f, int n) {
    int s = __float_as_int(f);
    unsigned u = (unsigned)s ^ (unsigned)((s >> 31) | 0x80000000);
    return ((unsigned long long)u << 32) | (unsigned)(0xffffffffu - (unsigned)n);
}

__device__ __forceinline__ void split_pair(float a, float b, uint32_t& hp, uint32_t& lp) {
    __nv_bfloat16 h0 = __float2bfloat16(a), h1 = __float2bfloat16(b);
    float r0 = a - __bfloat162float(h0), r1 = b - __bfloat162float(h1);
    __nv_bfloat16 l0 = __float2bfloat16(r0), l1 = __float2bfloat16(r1);
    hp = (uint32_t)__bfloat16_as_ushort(h0) | ((uint32_t)__bfloat16_as_ushort(h1) << 16);
    lp = (uint32_t)__bfloat16_as_ushort(l0) | ((uint32_t)__bfloat16_as_ushort(l1) << 16);
}

// ============================================================================
// Kernel 1: W -> bf16 hi/lo pre-swizzled tiles (blocks 0-127)
//           + query normalize -> bf16 hi/lo tiles + gate outputs (block 128)
// ============================================================================
__global__ void prep_all_kernel(const float* __restrict__ wproj,
                                const float* __restrict__ q,
                                const float* __restrict__ gate_logit,
                                float* __restrict__ out)
{
    int tid = threadIdx.x;
    if (blockIdx.x < 128) {
        int p = blockIdx.x * 256 + tid;   // 32768 pairs
        int row = p >> 7, pp = p & 127;
        int k = pp * 2, chunk = pp >> 5, kc = k & 63;
        float2 v = *(const float2*)(wproj + row * C + k);
        uint32_t hp, lp;
        split_pair(v.x, v.y, hp, lp);
        uint32_t off = (uint32_t)SW128(row * 128 + kc * 2);
        uint32_t idx = (uint32_t)chunk * 8192u + (off >> 2);
        ((uint32_t*)g_Whi4)[idx] = hp;
        ((uint32_t*)g_Wlo4)[idx] = lp;
    } else {
        int lane = tid & 31, w = tid >> 5;
        for (int r = w; r < B; r += 8) {
            const float4* qr = (const float4*)(q + r * C);
            float4 a = qr[lane*2], b = qr[lane*2 + 1];
            float ss = a.x*a.x + a.y*a.y + a.z*a.z + a.w*a.w
                     + b.x*b.x + b.y*b.y + b.z*b.z + b.w*b.w;
            #pragma unroll
            for (int o = 16; o > 0; o >>= 1) ss += __shfl_xor_sync(0xffffffffu, ss, o);
            float inv = 1.0f / fmaxf(sqrtf(ss), 1e-12f);
            a.x*=inv; a.y*=inv; a.z*=inv; a.w*=inv;
            b.x*=inv; b.y*=inv; b.z*=inv; b.w*=inv;
            // lane covers k = lane*8 .. lane*8+7 -> chunk = lane>>3, 16B unit (lane&7)
            uint32_t chunk = (uint32_t)(lane >> 3);
            uint32_t off = chunk * 8192u
                         + (uint32_t)(r * 128)
                         + ((uint32_t)((lane & 7) * 16) ^ (uint32_t)((r & 7) << 4));
            uint32_t i0 = off >> 2;
            uint32_t hp, lp;
            split_pair(a.x, a.y, hp, lp); g_qhi[i0+0] = hp; g_qlo[i0+0] = lp;
            split_pair(a.z, a.w, hp, lp); g_qhi[i0+1] = hp; g_qlo[i0+1] = lp;
            split_pair(b.x, b.y, hp, lp); g_qhi[i0+2] = hp; g_qlo[i0+2] = lp;
            split_pair(b.z, b.w, hp, lp); g_qhi[i0+3] = hp; g_qlo[i0+3] = lp;
        }
        if (tid < B) {
            float gate = 1.0f / (1.0f + expf(-gate_logit[0]));
            out[GATE_OFF + tid] = gate;
        }
    }
}

// ============================================================================
// Kernel 2: sims = qn @ norm(summaries)^T via mma.sync bf16 hi/lo
// Block: 256 threads (8 warps), tile M=64 (all queries) x N=128 summaries.
// K=256 in 4 chunks of 64; summaries converted on the fly; sinv at epilogue.
// ============================================================================
#define SIM_QHI  0          // 64 x 256 bf16 = 32KB (4 chunk tiles of 8KB)
#define SIM_QLO  32768
#define SIM_BHI  65536      // 128 x 64 bf16 = 16KB (current chunk)
#define SIM_BLO  81920
#define SIM_SSQ  98304      // 128 f32
#define SIM_SINV 98816      // 128 f32
#define SIM_TOTAL 99328

extern __shared__ char s_sm[];

__global__ __launch_bounds__(256, 2) void sims_mma_kernel(const float* __restrict__ summ)
{
    uint32_t smb = smem_u32(s_sm);
    int tid = threadIdx.x, lane = tid & 31, wn = tid >> 5;
    int n0 = blockIdx.x * 128;

    float* ssqS  = (float*)(s_sm + SIM_SSQ);
    float* sinvS = (float*)(s_sm + SIM_SINV);

    // load q tiles (pre-swizzled): 32KB each = 2048 uint4
    #pragma unroll
    for (int i = 0; i < 8; i++) {
        ((uint4*)(s_sm + SIM_QHI))[tid + i * 256] = ((const uint4*)g_qhi)[tid + i * 256];
        ((uint4*)(s_sm + SIM_QLO))[tid + i * 256] = ((const uint4*)g_qlo)[tid + i * 256];
    }
    if (tid < 128) ssqS[tid] = 0.0f;
    __syncthreads();

    // ldsm address pieces (mirrors fused kernel layout exactly)
    uint32_t kbA = (uint32_t)((lane >> 4) << 4);
    uint32_t swA = (uint32_t)((lane & 7) << 4);
    int rB = (lane & 7) + ((lane >> 4) << 3);
    uint32_t boffBase = (uint32_t)((wn * 16 + rB) * 128);
    uint32_t kbB = (uint32_t)(((lane >> 3) & 1) << 4);
    uint32_t swB = (uint32_t)((rB & 7) << 4);

    float acc[4][2][4];
    #pragma unroll
    for (int mt = 0; mt < 4; mt++)
        #pragma unroll
        for (int nt = 0; nt < 2; nt++)
            #pragma unroll
            for (int e = 0; e < 4; e++) acc[mt][nt][e] = 0.0f;

    int frow = tid >> 4;      // 0..15 base row
    int f4i  = tid & 15;      // float4 index within 64-k chunk

    for (int c = 0; c < 4; c++) {
        // load 128 rows x 64 k of summaries (guarded), sumsq, convert, store
        #pragma unroll
        for (int i = 0; i < 8; i++) {
            int r = frow + i * 16;
            int n = n0 + r;
            float4 v = make_float4(0.f, 0.f, 0.f, 0.f);
            if (n < N) v = *(const float4*)(summ + (size_t)n * C + c * 64 + f4i * 4);
            float s2 = v.x*v.x + v.y*v.y + v.z*v.z + v.w*v.w;
            #pragma unroll
            for (int o = 8; o > 0; o >>= 1) s2 += __shfl_xor_sync(0xffffffffu, s2, o);
            if (f4i == 0) ssqS[r] += s2;
            uint32_t hp0, lp0, hp1, lp1;
            split_pair(v.x, v.y, hp0, lp0);
            split_pair(v.z, v.w, hp1, lp1);
            uint32_t off = (uint32_t)(r * 128) + ((uint32_t)(f4i * 8) ^ (uint32_t)((r & 7) << 4));
            *(uint32_t*)(s_sm + SIM_BHI + off)     = hp0;
            *(uint32_t*)(s_sm + SIM_BHI + off + 4) = hp1;
            *(uint32_t*)(s_sm + SIM_BLO + off)     = lp0;
            *(uint32_t*)(s_sm + SIM_BLO + off + 4) = lp1;
        }
        __syncthreads();

        uint32_t qhiB = smb + SIM_QHI + c * 8192;
        uint32_t qloB = smb + SIM_QLO + c * 8192;
        uint32_t bhiB = smb + SIM_BHI;
        uint32_t bloB = smb + SIM_BLO;

        #pragma unroll
        for (int s = 0; s < 4; s++) {
            uint32_t koffA = ((uint32_t)(s * 32) + kbA) ^ swA;
            uint32_t koffB = ((uint32_t)(s * 32) + kbB) ^ swB;
            uint32_t ah[4][4], al[4][4];
            #pragma unroll
            for (int mt = 0; mt < 4; mt++) {
                uint32_t aoff = (uint32_t)((mt * 16 + (lane & 15)) * 128) + koffA;
                ldsm_x4(ah[mt], qhiB + aoff);
                ldsm_x4(al[mt], qloB + aoff);
            }
            uint32_t bh[4], bl[4];
            ldsm_x4(bh, bhiB + boffBase + koffB);
            ldsm_x4(bl, bloB + boffBase + koffB);
            #pragma unroll
            for (int mt = 0; mt < 4; mt++) {
                mma_bf16(acc[mt][0], ah[mt], &bh[0]);
                mma_bf16(acc[mt][0], ah[mt], &bl[0]);
                mma_bf16(acc[mt][0], al[mt], &bh[0]);
                mma_bf16(acc[mt][1], ah[mt], &bh[2]);
                mma_bf16(acc[mt][1], ah[mt], &bl[2]);
                mma_bf16(acc[mt][1], al[mt], &bh[2]);
            }
        }
        __syncthreads();
    }

    if (tid < 128) sinvS[tid] = 1.0f / fmaxf(sqrtf(ssqS[tid]), 1e-12f);
    __syncthreads();

    // epilogue: scale by sinv, -INF padding, store
    #pragma unroll
    for (int mt = 0; mt < 4; mt++) {
        #pragma unroll
        for (int nt = 0; nt < 2; nt++) {
            int nl = wn * 16 + nt * 8 + (lane & 3) * 2;
            int n = n0 + nl;
            if (n + 1 < NPAD) {
                float i0 = sinvS[nl], i1 = sinvS[nl + 1];
                #pragma unroll
                for (int half = 0; half < 2; half++) {
                    int m = mt * 16 + (lane >> 2) + half * 8;
                    float2 o;
                    o.x = (n     < N) ? acc[mt][nt][half*2]     * i0 : -INFINITY;
                    o.y = (n + 1 < N) ? acc[mt][nt][half*2 + 1] * i1 : -INFINITY;
                    *(float2*)(g_sims + (size_t)m * NPAD + n) = o;
                }
            }
        }
    }
}

// ============================================================================
// Kernel 3: partial top-8 per (query, eighth) — prefetched, shuffle select
// ============================================================================
__global__ __launch_bounds__(128) void topk_part_kernel()
{
    __shared__ unsigned long long wk[32];   // 4 warps x 8 winners

    int b = blockIdx.x >> 3, part = blockIdx.x & 7;
    int tid = threadIdx.x, lane = tid & 31, wid = tid >> 5;
    int nbase0 = part * PARTF;
    const float4* rowp = (const float4*)(g_sims + (size_t)b * NPAD + nbase0);

    float4 v[5];
    #pragma unroll
    for (int j = 0; j < 5; j++) {
        int idx = tid + j * 128;
        v[j] = rowp[idx < PART4 ? idx : PART4 - 1];
    }

    unsigned long long k[KTOP];
    #pragma unroll
    for (int j = 0; j < KTOP; j++) k[j] = 0ull;

    #pragma unroll
    for (int j = 0; j < 5; j++) {
        int idx = tid + j * 128;
        if (idx < PART4) {
            int nb = nbase0 + idx * 4;
            float vv[4] = {v[j].x, v[j].y, v[j].z, v[j].w};
            #pragma unroll
            for (int e = 0; e < 4; e++) {
                unsigned long long key = mk_key(vv[e], nb + e);
                if (key > k[KTOP-1]) {
                    int p = KTOP - 1;
                    #pragma unroll
                    for (int jj = KTOP - 1; jj > 0; jj--) {
                        if (key > k[jj-1]) { k[jj] = k[jj-1]; p = jj - 1; }
                        else break;
                    }
                    k[p] = key;
                }
            }
        }
    }

    #pragma unroll
    for (int it = 0; it < KTOP; it++) {
        unsigned long long m = k[0];
        #pragma unroll
        for (int o = 16; o > 0; o >>= 1) {
            unsigned long long t = __shfl_xor_sync(0xffffffffu, m, o);
            if (t > m) m = t;
        }
        if (k[0] == m) {
            #pragma unroll
            for (int j = 0; j < KTOP - 1; j++) k[j] = k[j+1];
            k[KTOP-1] = 0ull;
        }
        if (lane == 0) wk[wid * 8 + it] = m;
    }
    __syncthreads();

    if (wid == 0) {
        unsigned long long a = wk[lane];
        #pragma unroll
        for (int it = 0; it < KTOP; it++) {
            unsigned long long m = a;
            #pragma unroll
            for (int o = 16; o > 0; o >>= 1) {
                unsigned long long t = __shfl_xor_sync(0xffffffffu, m, o);
                if (t > m) m = t;
            }
            if (a == m) a = 0ull;
            if (lane == 0) g_cand_k[b * 64 + part * 8 + it] = m;
        }
    }
}

// ============================================================================
// Kernel 4: mma.sync fused  merge-topk -> gather -> (x@W^T + b) -> LN -> gate
// ============================================================================
#define SM_XHI   0              // 4 tiles x 16KB (128 rows x 128B)
#define SM_XLO   65536
#define SM_WHI   131072         // 256 rows x 128B = 32KB (current chunk)
#define SM_WLO   163840
#define SM_PAR   196608         // bias | gamma | beta (256 f32 each)
#define SM_RED   199680         // 4 x 128 float2
#define SM_PAGE  203776         // 2 ints
#define SM_TOTAL 203904

extern __shared__ char s_mm[];

__global__ __launch_bounds__(512, 1) void fused_mma_kernel(
    const float* __restrict__ templates,
    const float* __restrict__ bproj,
    const float* __restrict__ gamma_g,
    const float* __restrict__ beta_g,
    const float* __restrict__ gate_logit,
    float* __restrict__ out)
{
    uint32_t smb = smem_u32(s_mm);
    int tid = threadIdx.x, wid = tid >> 5, lane = tid & 31;
    int bid = blockIdx.x;
    int wm = wid & 3, wn = wid >> 2;

    float* biasS = (float*)(s_mm + SM_PAR);
    float* gamS  = biasS + 256;
    float* betS  = gamS + 256;
    float2* red2 = (float2*)(s_mm + SM_RED);   // [4][128]
    int*   pageS = (int*)(s_mm + SM_PAGE);
    if (tid < 256) { biasS[tid] = bproj[tid]; gamS[tid] = gamma_g[tid]; betS[tid] = beta_g[tid]; }

    // ---- in-block top-k merge: derive this block's 2 page indices ----
    if (wid == 0) {
        int qb = bid >> 2;
        int want0 = (bid & 3) * 2, want1 = want0 + 1;
        unsigned long long a = g_cand_k[qb * 64 + lane];
        unsigned long long c = g_cand_k[qb * 64 + lane + 32];
        #pragma unroll
        for (int sel = 0; sel < KTOP; sel++) {
            unsigned long long m = (a > c) ? a : c;
            #pragma unroll
            for (int o = 16; o > 0; o >>= 1) {
                unsigned long long t = __shfl_xor_sync(0xffffffffu, m, o);
                if (t > m) m = t;
            }
            if (a == m) a = 0ull;
            else if (c == m) c = 0ull;
            if (lane == 0) {
                int idx = (int)(0xffffffffu - (unsigned)(m & 0xffffffffu));
                if (sel == want0) pageS[0] = idx;
                if (sel == want1) pageS[1] = idx;
            }
        }
    }
    __syncthreads();
    int p0 = pageS[0], p1 = pageS[1];

    // ---- gather + convert x (2 pages = 128 rows x 256 k) into hi/lo tiles ----
    for (int i = tid; i < 16384; i += 512) {            // bf16 pairs
        int row = i >> 7, pp = i & 127;
        int k = pp * 2, chunk = pp >> 5, kc = k & 63;
        const float* src = templates + (size_t)(row < 64 ? p0 : p1) * PAGE + (row & 63) * C + k;
        float2 v = *(const float2*)src;
        uint32_t hp, lp;
        split_pair(v.x, v.y, hp, lp);
        uint32_t off = (uint32_t)chunk * 16384u + (uint32_t)(row * 128) + (uint32_t)((kc * 2) ^ ((row & 7) << 4));
        *(uint32_t*)(s_mm + SM_XHI + off) = hp;
        *(uint32_t*)(s_mm + SM_XLO + off) = lp;
    }

    // ---- precomputed ldmatrix address pieces ----
    int arow0 = wm * 32 + (lane & 15);
    uint32_t aoff0 = (uint32_t)(arow0 * 128);
    uint32_t aoff1 = aoff0 + 16 * 128;
    uint32_t kbA = (uint32_t)((lane >> 4) << 4);
    uint32_t swA = (uint32_t)((lane & 7) << 4);
    int rB = (lane & 7) + ((lane >> 4) << 3);
    uint32_t boffBase = (uint32_t)((wn * 64 + rB) * 128);
    uint32_t kbB = (uint32_t)(((lane >> 3) & 1) << 4);
    uint32_t swB = (uint32_t)((rB & 7) << 4);

    float acc[2][8][4];
    #pragma unroll
    for (int mt = 0; mt < 2; mt++)
        #pragma unroll
        for (int nt = 0; nt < 8; nt++)
            #pragma unroll
            for (int e = 0; e < 4; e++) acc[mt][nt][e] = 0.0f;

    uint4* dh = (uint4*)(s_mm + SM_WHI);
    uint4* dl = (uint4*)(s_mm + SM_WLO);

    for (int c = 0; c < 4; c++) {
        const uint4* sh = g_Whi4 + c * 2048;
        const uint4* sl = g_Wlo4 + c * 2048;
        #pragma unroll
        for (int i = 0; i < 4; i++) {
            dh[tid + i * 512] = sh[tid + i * 512];
            dl[tid + i * 512] = sl[tid + i * 512];
        }
        __syncthreads();

        uint32_t xbaseH = smb + SM_XHI + c * 16384;
        uint32_t xbaseL = smb + SM_XLO + c * 16384;
        uint32_t wbaseH = smb + SM_WHI;
        uint32_t wbaseL = smb + SM_WLO;

        #pragma unroll
        for (int s = 0; s < 4; s++) {
            uint32_t ka = (uint32_t)(s * 32) + kbA;
            uint32_t koffA = ka ^ swA;
            uint32_t xh[2][4], xl[2][4];
            ldsm_x4(xh[0], xbaseH + aoff0 + koffA);
            ldsm_x4(xh[1], xbaseH + aoff1 + koffA);
            ldsm_x4(xl[0], xbaseL + aoff0 + koffA);
            ldsm_x4(xl[1], xbaseL + aoff1 + koffA);

            uint32_t kb = (uint32_t)(s * 32) + kbB;
            uint32_t koffB = kb ^ swB;
            #pragma unroll
            for (int p = 0; p < 4; p++) {
                uint32_t boff = boffBase + (uint32_t)(p * 16 * 128) + koffB;
                uint32_t wh[4], wl[4];
                ldsm_x4(wh, wbaseH + boff);
                ldsm_x4(wl, wbaseL + boff);
                #pragma unroll
                for (int mt = 0; mt < 2; mt++) {
                    mma_bf16(acc[mt][2*p],   xh[mt], &wh[0]);
                    mma_bf16(acc[mt][2*p],   xh[mt], &wl[0]);
                    mma_bf16(acc[mt][2*p],   xl[mt], &wh[0]);
                    mma_bf16(acc[mt][2*p+1], xh[mt], &wh[2]);
                    mma_bf16(acc[mt][2*p+1], xh[mt], &wl[2]);
                    mma_bf16(acc[mt][2*p+1], xl[mt], &wh[2]);
                }
            }
        }
        __syncthreads();
    }

    // ---- LayerNorm epilogue ----
    int colb = wn * 64 + (lane & 3) * 2;

    #pragma unroll
    for (int mt = 0; mt < 2; mt++) {
        #pragma unroll
        for (int half = 0; half < 2; half++) {
            float s1 = 0.f, s2 = 0.f;
            #pragma unroll
            for (int nt = 0; nt < 8; nt++) {
                int col0 = colb + nt * 8;
                float h0 = acc[mt][nt][half*2]     + biasS[col0];
                float h1 = acc[mt][nt][half*2 + 1] + biasS[col0 + 1];
                s1 += h0 + h1;
                s2 += h0 * h0 + h1 * h1;
            }
            s1 += __shfl_xor_sync(0xffffffffu, s1, 1);
            s2 += __shfl_xor_sync(0xffffffffu, s2, 1);
            s1 += __shfl_xor_sync(0xffffffffu, s1, 2);
            s2 += __shfl_xor_sync(0xffffffffu, s2, 2);
            if ((lane & 3) == 0) {
                int row = wm * 32 + mt * 16 + half * 8 + (lane >> 2);
                red2[wn * 128 + row] = make_float2(s1, s2);
            }
        }
    }
    __syncthreads();

    float gate = 1.0f / (1.0f + expf(-gate_logit[0]));

    #pragma unroll
    for (int mt = 0; mt < 2; mt++) {
        #pragma unroll
        for (int half = 0; half < 2; half++) {
            int row = wm * 32 + mt * 16 + half * 8 + (lane >> 2);
            float2 r0 = red2[0 * 128 + row];
            float2 r1 = red2[1 * 128 + row];
            float2 r2 = red2[2 * 128 + row];
            float2 r3 = red2[3 * 128 + row];
            float s1 = r0.x + r1.x + r2.x + r3.x;
            float s2 = r0.y + r1.y + r2.y + r3.y;
            float mu   = s1 * (1.0f / 256.0f);
            float var  = s2 * (1.0f / 256.0f) - mu * mu;
            float rstd = rsqrtf(var + 1e-5f);

            float* orow = out + ((size_t)bid * 128 + row) * C;
            #pragma unroll
            for (int nt = 0; nt < 8; nt++) {
                int col0 = colb + nt * 8;
                float h0 = acc[mt][nt][half*2]     + biasS[col0];
                float h1 = acc[mt][nt][half*2 + 1] + biasS[col0 + 1];
                float2 o;
                o.x = ((h0 - mu) * rstd * gamS[col0]     + betS[col0])     * gate;
                o.y = ((h1 - mu) * rstd * gamS[col0 + 1] + betS[col0 + 1]) * gate;
                *(float2*)(orow + col0) = o;
            }
        }
    }
}

// ============================================================================
// launch
// ============================================================================
extern "C" void kernel_launch(void* const* d_in, const int* in_sizes, int n_in,
                              void* d_out, int out_size)
{
    const float* query = (const float*)d_in[0];
    const float* summ  = (const float*)d_in[1];
    const float* templ = (const float*)d_in[2];
    const float* wproj = (const float*)d_in[3];
    const float* bproj = (const float*)d_in[4];
    const float* gamma = (const float*)d_in[5];
    const float* beta  = (const float*)d_in[6];
    const float* glog  = (const float*)d_in[7];
    float* out = (float*)d_out;

    cudaFuncSetAttribute(sims_mma_kernel, cudaFuncAttributeMaxDynamicSharedMemorySize, SIM_TOTAL);
    cudaFuncSetAttribute(fused_mma_kernel, cudaFuncAttributeMaxDynamicSharedMemorySize, SM_TOTAL);

    prep_all_kernel<<<129, 256>>>(wproj, query, glog, out);
    sims_mma_kernel<<<(NPAD + 127) / 128, 256, SIM_TOTAL>>>(summ);
    topk_part_kernel<<<B * PARTS, 128>>>();
    fused_mma_kernel<<<B * KTOP / 2, 512, SM_TOTAL>>>(templ, bproj, gamma, beta, glog, out);
}

// round 10
// speedup vs baseline: 2.6907x; 1.1190x over previous
#include <cuda_runtime.h>
#include <cuda_bf16.h>
#include <math.h>
#include <stdint.h>

#define B   64
#define C   256
#define N   20000
#define NPAD 20032          // 313 * 64
#define NT  64
#define KTOP 8
#define PAGE (NT*C)         // 16384 floats per template page
#define GATE_OFF (B*KTOP*NT*C)
#define PARTS 8
#define PARTF 2504          // NPAD / PARTS floats
#define PART4 626           // PARTF / 4

// ---- device scratch ----
__device__ float g_sims[B*NPAD];
__device__ unsigned long long g_cand_k[B*64];
__device__ uint4 g_Whi4[8192];   // 4 chunk-tiles of 256 rows x 64 bf16 (128B rows, XOR-swizzled)
__device__ uint4 g_Wlo4[8192];
__device__ uint32_t g_qhi[8192]; // 4 chunk-tiles of 64 rows x 64 bf16 (normalized q, swizzled) = 32KB
__device__ uint32_t g_qlo[8192];

#define SW128(b) ((b) ^ (((b) >> 3) & 0x70))

__device__ __forceinline__ uint32_t smem_u32(const void* p) {
    uint32_t a;
    asm("{ .reg .u64 t; cvta.to.shared.u64 t, %1; cvt.u32.u64 %0, t; }" : "=r"(a) : "l"(p));
    return a;
}

__device__ __forceinline__ void ldsm_x4(uint32_t* r, uint32_t addr) {
    asm volatile("ldmatrix.sync.aligned.m8n8.x4.shared.b16 {%0,%1,%2,%3}, [%4];"
                 : "=r"(r[0]), "=r"(r[1]), "=r"(r[2]), "=r"(r[3]) : "r"(addr));
}

__device__ __forceinline__ void mma_bf16(float* c, const uint32_t* a, const uint32_t* b) {
    asm volatile(
        "mma.sync.aligned.m16n8k16.row.col.f32.bf16.bf16.f32 "
        "{%0,%1,%2,%3}, {%4,%5,%6,%7}, {%8,%9}, {%0,%1,%2,%3};"
        : "+f"(c[0]), "+f"(c[1]), "+f"(c[2]), "+f"(c[3])
        : "r"(a[0]), "r"(a[1]), "r"(a[2]), "r"(a[3]), "r"(b[0]), "r"(b[1]));
}

__device__ __forceinline__ void cp_async8(uint32_t dst, const void* src) {
    asm volatile("cp.async.ca.shared.global [%0], [%1], 8;" :: "r"(dst), "l"(src));
}
__device__ __forceinline__ void cp_async16(uint32_t dst, const void* src) {
    asm volatile("cp.async.cg.shared.global [%0], [%1], 16;" :: "r"(dst), "l"(src));
}
#define CP_COMMIT() asm volatile("cp.async.commit_group;" ::: "memory")
#define CP_WAIT(n)  asm volatile("cp.async.wait_group %0;" :: "n"(n) : "memory")

// monotone key: bigger value -> bigger key; tie -> lower index bigger key
__device__ __forceinline__ unsigned long long mk_key(float f, int n) {
    int s = __float_as_int(f);
    unsigned u = (unsigned)s ^ (unsigned)((s >> 31) | 0x80000000);
    return ((unsigned long long)u << 32) | (unsigned)(0xffffffffu - (unsigned)n);
}

__device__ __forceinline__ void split_pair(float a, float b, uint32_t& hp, uint32_t& lp) {
    __nv_bfloat16 h0 = __float2bfloat16(a), h1 = __float2bfloat16(b);
    float r0 = a - __bfloat162float(h0), r1 = b - __bfloat162float(h1);
    __nv_bfloat16 l0 = __float2bfloat16(r0), l1 = __float2bfloat16(r1);
    hp = (uint32_t)__bfloat16_as_ushort(h0) | ((uint32_t)__bfloat16_as_ushort(h1) << 16);
    lp = (uint32_t)__bfloat16_as_ushort(l0) | ((uint32_t)__bfloat16_as_ushort(l1) << 16);
}

// ============================================================================
// Kernel 1: W -> bf16 hi/lo pre-swizzled tiles (blocks 0-127)
//           + query normalize -> bf16 hi/lo tiles + gate outputs (block 128)
// ============================================================================
__global__ void prep_all_kernel(const float* __restrict__ wproj,
                                const float* __restrict__ q,
                                const float* __restrict__ gate_logit,
                                float* __restrict__ out)
{
    int tid = threadIdx.x;
    if (blockIdx.x < 128) {
        int p = blockIdx.x * 256 + tid;   // 32768 pairs
        int row = p >> 7, pp = p & 127;
        int k = pp * 2, chunk = pp >> 5, kc = k & 63;
        float2 v = *(const float2*)(wproj + row * C + k);
        uint32_t hp, lp;
        split_pair(v.x, v.y, hp, lp);
        uint32_t off = (uint32_t)SW128(row * 128 + kc * 2);
        uint32_t idx = (uint32_t)chunk * 8192u + (off >> 2);
        ((uint32_t*)g_Whi4)[idx] = hp;
        ((uint32_t*)g_Wlo4)[idx] = lp;
    } else {
        int lane = tid & 31, w = tid >> 5;
        for (int r = w; r < B; r += 8) {
            const float4* qr = (const float4*)(q + r * C);
            float4 a = qr[lane*2], b = qr[lane*2 + 1];
            float ss = a.x*a.x + a.y*a.y + a.z*a.z + a.w*a.w
                     + b.x*b.x + b.y*b.y + b.z*b.z + b.w*b.w;
            #pragma unroll
            for (int o = 16; o > 0; o >>= 1) ss += __shfl_xor_sync(0xffffffffu, ss, o);
            float inv = 1.0f / fmaxf(sqrtf(ss), 1e-12f);
            a.x*=inv; a.y*=inv; a.z*=inv; a.w*=inv;
            b.x*=inv; b.y*=inv; b.z*=inv; b.w*=inv;
            uint32_t chunk = (uint32_t)(lane >> 3);
            uint32_t off = chunk * 8192u
                         + (uint32_t)(r * 128)
                         + ((uint32_t)((lane & 7) * 16) ^ (uint32_t)((r & 7) << 4));
            uint32_t i0 = off >> 2;
            uint32_t hp, lp;
            split_pair(a.x, a.y, hp, lp); g_qhi[i0+0] = hp; g_qlo[i0+0] = lp;
            split_pair(a.z, a.w, hp, lp); g_qhi[i0+1] = hp; g_qlo[i0+1] = lp;
            split_pair(b.x, b.y, hp, lp); g_qhi[i0+2] = hp; g_qlo[i0+2] = lp;
            split_pair(b.z, b.w, hp, lp); g_qhi[i0+3] = hp; g_qlo[i0+3] = lp;
        }
        if (tid < B) {
            float gate = 1.0f / (1.0f + expf(-gate_logit[0]));
            out[GATE_OFF + tid] = gate;
        }
    }
}

// ============================================================================
// Kernel 2: sims = qn @ norm(summaries)^T via mma.sync bf16 hi/lo
// ============================================================================
#define SIM_QHI  0          // 64 x 256 bf16 = 32KB (4 chunk tiles of 8KB)
#define SIM_QLO  32768
#define SIM_BHI  65536      // 128 x 64 bf16 = 16KB (current chunk)
#define SIM_BLO  81920
#define SIM_SSQ  98304      // 128 f32
#define SIM_SINV 98816      // 128 f32
#define SIM_TOTAL 99328

extern __shared__ char s_sm[];

__global__ __launch_bounds__(256, 2) void sims_mma_kernel(const float* __restrict__ summ)
{
    uint32_t smb = smem_u32(s_sm);
    int tid = threadIdx.x, lane = tid & 31, wn = tid >> 5;
    int n0 = blockIdx.x * 128;

    float* ssqS  = (float*)(s_sm + SIM_SSQ);
    float* sinvS = (float*)(s_sm + SIM_SINV);

    // load q tiles (pre-swizzled): 32KB each = 2048 uint4
    #pragma unroll
    for (int i = 0; i < 8; i++) {
        ((uint4*)(s_sm + SIM_QHI))[tid + i * 256] = ((const uint4*)g_qhi)[tid + i * 256];
        ((uint4*)(s_sm + SIM_QLO))[tid + i * 256] = ((const uint4*)g_qlo)[tid + i * 256];
    }
    if (tid < 128) ssqS[tid] = 0.0f;
    __syncthreads();

    uint32_t kbA = (uint32_t)((lane >> 4) << 4);
    uint32_t swA = (uint32_t)((lane & 7) << 4);
    int rB = (lane & 7) + ((lane >> 4) << 3);
    uint32_t boffBase = (uint32_t)((wn * 16 + rB) * 128);
    uint32_t kbB = (uint32_t)(((lane >> 3) & 1) << 4);
    uint32_t swB = (uint32_t)((rB & 7) << 4);

    float acc[4][2][4];
    #pragma unroll
    for (int mt = 0; mt < 4; mt++)
        #pragma unroll
        for (int nt = 0; nt < 2; nt++)
            #pragma unroll
            for (int e = 0; e < 4; e++) acc[mt][nt][e] = 0.0f;

    int frow = tid >> 4;      // 0..15 base row
    int f4i  = tid & 15;      // float4 index within 64-k chunk

    for (int c = 0; c < 4; c++) {
        #pragma unroll
        for (int i = 0; i < 8; i++) {
            int r = frow + i * 16;
            int n = n0 + r;
            float4 v = make_float4(0.f, 0.f, 0.f, 0.f);
            if (n < N) v = *(const float4*)(summ + (size_t)n * C + c * 64 + f4i * 4);
            float s2 = v.x*v.x + v.y*v.y + v.z*v.z + v.w*v.w;
            #pragma unroll
            for (int o = 8; o > 0; o >>= 1) s2 += __shfl_xor_sync(0xffffffffu, s2, o);
            if (f4i == 0) ssqS[r] += s2;
            uint32_t hp0, lp0, hp1, lp1;
            split_pair(v.x, v.y, hp0, lp0);
            split_pair(v.z, v.w, hp1, lp1);
            uint32_t off = (uint32_t)(r * 128) + ((uint32_t)(f4i * 8) ^ (uint32_t)((r & 7) << 4));
            *(uint32_t*)(s_sm + SIM_BHI + off)     = hp0;
            *(uint32_t*)(s_sm + SIM_BHI + off + 4) = hp1;
            *(uint32_t*)(s_sm + SIM_BLO + off)     = lp0;
            *(uint32_t*)(s_sm + SIM_BLO + off + 4) = lp1;
        }
        __syncthreads();

        uint32_t qhiB = smb + SIM_QHI + c * 8192;
        uint32_t qloB = smb + SIM_QLO + c * 8192;
        uint32_t bhiB = smb + SIM_BHI;
        uint32_t bloB = smb + SIM_BLO;

        #pragma unroll
        for (int s = 0; s < 4; s++) {
            uint32_t koffA = ((uint32_t)(s * 32) + kbA) ^ swA;
            uint32_t koffB = ((uint32_t)(s * 32) + kbB) ^ swB;
            uint32_t ah[4][4], al[4][4];
            #pragma unroll
            for (int mt = 0; mt < 4; mt++) {
                uint32_t aoff = (uint32_t)((mt * 16 + (lane & 15)) * 128) + koffA;
                ldsm_x4(ah[mt], qhiB + aoff);
                ldsm_x4(al[mt], qloB + aoff);
            }
            uint32_t bh[4], bl[4];
            ldsm_x4(bh, bhiB + boffBase + koffB);
            ldsm_x4(bl, bloB + boffBase + koffB);
            #pragma unroll
            for (int mt = 0; mt < 4; mt++) {
                mma_bf16(acc[mt][0], ah[mt], &bh[0]);
                mma_bf16(acc[mt][0], ah[mt], &bl[0]);
                mma_bf16(acc[mt][0], al[mt], &bh[0]);
                mma_bf16(acc[mt][1], ah[mt], &bh[2]);
                mma_bf16(acc[mt][1], ah[mt], &bl[2]);
                mma_bf16(acc[mt][1], al[mt], &bh[2]);
            }
        }
        __syncthreads();
    }

    if (tid < 128) sinvS[tid] = 1.0f / fmaxf(sqrtf(ssqS[tid]), 1e-12f);
    __syncthreads();

    #pragma unroll
    for (int mt = 0; mt < 4; mt++) {
        #pragma unroll
        for (int nt = 0; nt < 2; nt++) {
            int nl = wn * 16 + nt * 8 + (lane & 3) * 2;
            int n = n0 + nl;
            if (n + 1 < NPAD) {
                float i0 = sinvS[nl], i1 = sinvS[nl + 1];
                #pragma unroll
                for (int half = 0; half < 2; half++) {
                    int m = mt * 16 + (lane >> 2) + half * 8;
                    float2 o;
                    o.x = (n     < N) ? acc[mt][nt][half*2]     * i0 : -INFINITY;
                    o.y = (n + 1 < N) ? acc[mt][nt][half*2 + 1] * i1 : -INFINITY;
                    *(float2*)(g_sims + (size_t)m * NPAD + n) = o;
                }
            }
        }
    }
}

// ============================================================================
// Kernel 3: partial top-8 per (query, eighth) — prefetched, shuffle select
// ============================================================================
__global__ __launch_bounds__(128) void topk_part_kernel()
{
    __shared__ unsigned long long wk[32];   // 4 warps x 8 winners

    int b = blockIdx.x >> 3, part = blockIdx.x & 7;
    int tid = threadIdx.x, lane = tid & 31, wid = tid >> 5;
    int nbase0 = part * PARTF;
    const float4* rowp = (const float4*)(g_sims + (size_t)b * NPAD + nbase0);

    float4 v[5];
    #pragma unroll
    for (int j = 0; j < 5; j++) {
        int idx = tid + j * 128;
        v[j] = rowp[idx < PART4 ? idx : PART4 - 1];
    }

    unsigned long long k[KTOP];
    #pragma unroll
    for (int j = 0; j < KTOP; j++) k[j] = 0ull;

    #pragma unroll
    for (int j = 0; j < 5; j++) {
        int idx = tid + j * 128;
        if (idx < PART4) {
            int nb = nbase0 + idx * 4;
            float vv[4] = {v[j].x, v[j].y, v[j].z, v[j].w};
            #pragma unroll
            for (int e = 0; e < 4; e++) {
                unsigned long long key = mk_key(vv[e], nb + e);
                if (key > k[KTOP-1]) {
                    int p = KTOP - 1;
                    #pragma unroll
                    for (int jj = KTOP - 1; jj > 0; jj--) {
                        if (key > k[jj-1]) { k[jj] = k[jj-1]; p = jj - 1; }
                        else break;
                    }
                    k[p] = key;
                }
            }
        }
    }

    #pragma unroll
    for (int it = 0; it < KTOP; it++) {
        unsigned long long m = k[0];
        #pragma unroll
        for (int o = 16; o > 0; o >>= 1) {
            unsigned long long t = __shfl_xor_sync(0xffffffffu, m, o);
            if (t > m) m = t;
        }
        if (k[0] == m) {
            #pragma unroll
            for (int j = 0; j < KTOP - 1; j++) k[j] = k[j+1];
            k[KTOP-1] = 0ull;
        }
        if (lane == 0) wk[wid * 8 + it] = m;
    }
    __syncthreads();

    if (wid == 0) {
        unsigned long long a = wk[lane];
        #pragma unroll
        for (int it = 0; it < KTOP; it++) {
            unsigned long long m = a;
            #pragma unroll
            for (int o = 16; o > 0; o >>= 1) {
                unsigned long long t = __shfl_xor_sync(0xffffffffu, m, o);
                if (t > m) m = t;
            }
            if (a == m) a = 0ull;
            if (lane == 0) g_cand_k[b * 64 + part * 8 + it] = m;
        }
    }
}

// ============================================================================
// Kernel 4: pipelined mma.sync fused
// merge-topk -> cp.async-staged gather -> (x@W^T + b) -> LN -> gate -> out
// Per K-chunk (64): stage x fp32 via cp.async (double buf), W via cp.async,
// convert own staged data to bf16 hi/lo, MMA. DRAM/L2 latency hidden.
// ============================================================================
#define SM_XS0   0              // 32KB fp32 stage A (128 rows x 64k)
#define SM_XS1   32768          // 32KB fp32 stage B
#define SM_XHI   65536          // 16KB bf16 hi chunk (128 rows x 128B)
#define SM_XLO   81920          // 16KB bf16 lo chunk
#define SM_WHI   98304          // 32KB (256 rows x 128B, current chunk)
#define SM_WLO   131072         // 32KB
#define SM_PAR   163840         // bias | gamma | beta (256 f32 each)
#define SM_RED   166912         // 4 x 128 float2
#define SM_PAGE  171008         // 2 ints
#define SM_TOTAL 171136

extern __shared__ char s_mm[];

__global__ __launch_bounds__(512, 1) void fused_mma_kernel(
    const float* __restrict__ templates,
    const float* __restrict__ bproj,
    const float* __restrict__ gamma_g,
    const float* __restrict__ beta_g,
    const float* __restrict__ gate_logit,
    float* __restrict__ out)
{
    uint32_t smb = smem_u32(s_mm);
    int tid = threadIdx.x, wid = tid >> 5, lane = tid & 31;
    int bid = blockIdx.x;
    int wm = wid & 3, wn = wid >> 2;

    float* biasS = (float*)(s_mm + SM_PAR);
    float* gamS  = biasS + 256;
    float* betS  = gamS + 256;
    float2* red2 = (float2*)(s_mm + SM_RED);   // [4][128]
    int*   pageS = (int*)(s_mm + SM_PAGE);
    if (tid < 256) { biasS[tid] = bproj[tid]; gamS[tid] = gamma_g[tid]; betS[tid] = beta_g[tid]; }

    // ---- in-block top-k merge: derive this block's 2 page indices ----
    if (wid == 0) {
        int qb = bid >> 2;
        int want0 = (bid & 3) * 2, want1 = want0 + 1;
        unsigned long long a = g_cand_k[qb * 64 + lane];
        unsigned long long c = g_cand_k[qb * 64 + lane + 32];
        #pragma unroll
        for (int sel = 0; sel < KTOP; sel++) {
            unsigned long long m = (a > c) ? a : c;
            #pragma unroll
            for (int o = 16; o > 0; o >>= 1) {
                unsigned long long t = __shfl_xor_sync(0xffffffffu, m, o);
                if (t > m) m = t;
            }
            if (a == m) a = 0ull;
            else if (c == m) c = 0ull;
            if (lane == 0) {
                int idx = (int)(0xffffffffu - (unsigned)(m & 0xffffffffu));
                if (sel == want0) pageS[0] = idx;
                if (sel == want1) pageS[1] = idx;
            }
        }
    }
    __syncthreads();
    int p0 = pageS[0], p1 = pageS[1];

    // per-thread staged-pair geometry (fixed across chunks)
    // pp = tid + j*512 ; row = pp>>5 ; kp = pp&31  (32 fp32-pairs per row chunk)
    // ---- prologue: prefetch x chunk 0 into stage A ----
    {
        #pragma unroll
        for (int j = 0; j < 8; j++) {
            int pp = tid + j * 512;
            int row = pp >> 5, kp = pp & 31;
            const float* src = templates + (size_t)(row < 64 ? p0 : p1) * PAGE
                             + (row & 63) * C + kp * 2;
            cp_async8(smb + SM_XS0 + (uint32_t)pp * 8, src);
        }
        CP_COMMIT();
    }

    // ldsm address pieces
    int arow0 = wm * 32 + (lane & 15);
    uint32_t aoff0 = (uint32_t)(arow0 * 128);
    uint32_t aoff1 = aoff0 + 16 * 128;
    uint32_t kbA = (uint32_t)((lane >> 4) << 4);
    uint32_t swA = (uint32_t)((lane & 7) << 4);
    int rB = (lane & 7) + ((lane >> 4) << 3);
    uint32_t boffBase = (uint32_t)((wn * 64 + rB) * 128);
    uint32_t kbB = (uint32_t)(((lane >> 3) & 1) << 4);
    uint32_t swB = (uint32_t)((rB & 7) << 4);

    float acc[2][8][4];
    #pragma unroll
    for (int mt = 0; mt < 2; mt++)
        #pragma unroll
        for (int nt = 0; nt < 8; nt++)
            #pragma unroll
            for (int e = 0; e < 4; e++) acc[mt][nt][e] = 0.0f;

    #pragma unroll
    for (int c = 0; c < 4; c++) {
        __syncthreads();    // prior MMA done reading XHI/XLO/WHI/WLO

        uint32_t stCur = (c & 1) ? (uint32_t)SM_XS1 : (uint32_t)SM_XS0;
        uint32_t stNxt = (c & 1) ? (uint32_t)SM_XS0 : (uint32_t)SM_XS1;

        // W chunk c via cp.async (pre-swizzled, L2-hot)
        #pragma unroll
        for (int i = 0; i < 4; i++) {
            cp_async16(smb + SM_WHI + (uint32_t)(tid + i * 512) * 16,
                       g_Whi4 + c * 2048 + tid + i * 512);
            cp_async16(smb + SM_WLO + (uint32_t)(tid + i * 512) * 16,
                       g_Wlo4 + c * 2048 + tid + i * 512);
        }
        CP_COMMIT();

        // prefetch x chunk c+1 into the other stage buffer
        if (c < 3) {
            #pragma unroll
            for (int j = 0; j < 8; j++) {
                int pp = tid + j * 512;
                int row = pp >> 5, kp = pp & 31;
                const float* src = templates + (size_t)(row < 64 ? p0 : p1) * PAGE
                                 + (row & 63) * C + (c + 1) * 64 + kp * 2;
                cp_async8(smb + stNxt + (uint32_t)pp * 8, src);
            }
            CP_COMMIT();
            CP_WAIT(2);     // stage_c arrived (W_c, stage_{c+1} may fly)
        } else {
            CP_WAIT(1);     // stage_3 arrived (W_3 may fly)
        }

        // convert OWN staged pairs to bf16 hi/lo (no barrier needed: own data)
        #pragma unroll
        for (int j = 0; j < 8; j++) {
            int pp = tid + j * 512;
            int row = pp >> 5, kp = pp & 31;
            float2 v = *(float2*)(s_mm + stCur + (uint32_t)pp * 8);
            uint32_t hp, lp;
            split_pair(v.x, v.y, hp, lp);
            uint32_t off = (uint32_t)(row * 128) + (uint32_t)((kp * 4) ^ ((row & 7) << 4));
            *(uint32_t*)(s_mm + SM_XHI + off) = hp;
            *(uint32_t*)(s_mm + SM_XLO + off) = lp;
        }

        if (c < 3) { CP_WAIT(1); } else { CP_WAIT(0); }   // W_c arrived
        __syncthreads();    // x tiles + W visible to all warps

        uint32_t xbaseH = smb + SM_XHI;
        uint32_t xbaseL = smb + SM_XLO;
        uint32_t wbaseH = smb + SM_WHI;
        uint32_t wbaseL = smb + SM_WLO;

        #pragma unroll
        for (int s = 0; s < 4; s++) {
            uint32_t ka = (uint32_t)(s * 32) + kbA;
            uint32_t koffA = ka ^ swA;
            uint32_t xh[2][4], xl[2][4];
            ldsm_x4(xh[0], xbaseH + aoff0 + koffA);
            ldsm_x4(xh[1], xbaseH + aoff1 + koffA);
            ldsm_x4(xl[0], xbaseL + aoff0 + koffA);
            ldsm_x4(xl[1], xbaseL + aoff1 + koffA);

            uint32_t kb = (uint32_t)(s * 32) + kbB;
            uint32_t koffB = kb ^ swB;
            #pragma unroll
            for (int p = 0; p < 4; p++) {
                uint32_t boff = boffBase + (uint32_t)(p * 16 * 128) + koffB;
                uint32_t wh[4], wl[4];
                ldsm_x4(wh, wbaseH + boff);
                ldsm_x4(wl, wbaseL + boff);
                #pragma unroll
                for (int mt = 0; mt < 2; mt++) {
                    mma_bf16(acc[mt][2*p],   xh[mt], &wh[0]);
                    mma_bf16(acc[mt][2*p],   xh[mt], &wl[0]);
                    mma_bf16(acc[mt][2*p],   xl[mt], &wh[0]);
                    mma_bf16(acc[mt][2*p+1], xh[mt], &wh[2]);
                    mma_bf16(acc[mt][2*p+1], xh[mt], &wl[2]);
                    mma_bf16(acc[mt][2*p+1], xl[mt], &wh[2]);
                }
            }
        }
    }

    // ---- LayerNorm epilogue ----
    int colb = wn * 64 + (lane & 3) * 2;

    #pragma unroll
    for (int mt = 0; mt < 2; mt++) {
        #pragma unroll
        for (int half = 0; half < 2; half++) {
            float s1 = 0.f, s2 = 0.f;
            #pragma unroll
            for (int nt = 0; nt < 8; nt++) {
                int col0 = colb + nt * 8;
                float h0 = acc[mt][nt][half*2]     + biasS[col0];
                float h1 = acc[mt][nt][half*2 + 1] + biasS[col0 + 1];
                s1 += h0 + h1;
                s2 += h0 * h0 + h1 * h1;
            }
            s1 += __shfl_xor_sync(0xffffffffu, s1, 1);
            s2 += __shfl_xor_sync(0xffffffffu, s2, 1);
            s1 += __shfl_xor_sync(0xffffffffu, s1, 2);
            s2 += __shfl_xor_sync(0xffffffffu, s2, 2);
            if ((lane & 3) == 0) {
                int row = wm * 32 + mt * 16 + half * 8 + (lane >> 2);
                red2[wn * 128 + row] = make_float2(s1, s2);
            }
        }
    }
    __syncthreads();

    float gate = 1.0f / (1.0f + expf(-gate_logit[0]));

    #pragma unroll
    for (int mt = 0; mt < 2; mt++) {
        #pragma unroll
        for (int half = 0; half < 2; half++) {
            int row = wm * 32 + mt * 16 + half * 8 + (lane >> 2);
            float2 r0 = red2[0 * 128 + row];
            float2 r1 = red2[1 * 128 + row];
            float2 r2 = red2[2 * 128 + row];
            float2 r3 = red2[3 * 128 + row];
            float s1 = r0.x + r1.x + r2.x + r3.x;
            float s2 = r0.y + r1.y + r2.y + r3.y;
            float mu   = s1 * (1.0f / 256.0f);
            float var  = s2 * (1.0f / 256.0f) - mu * mu;
            float rstd = rsqrtf(var + 1e-5f);

            float* orow = out + ((size_t)bid * 128 + row) * C;
            #pragma unroll
            for (int nt = 0; nt < 8; nt++) {
                int col0 = colb + nt * 8;
                float h0 = acc[mt][nt][half*2]     + biasS[col0];
                float h1 = acc[mt][nt][half*2 + 1] + biasS[col0 + 1];
                float2 o;
                o.x = ((h0 - mu) * rstd * gamS[col0]     + betS[col0])     * gate;
                o.y = ((h1 - mu) * rstd * gamS[col0 + 1] + betS[col0 + 1]) * gate;
                *(float2*)(orow + col0) = o;
            }
        }
    }
}

// ============================================================================
// launch
// ============================================================================
extern "C" void kernel_launch(void* const* d_in, const int* in_sizes, int n_in,
                              void* d_out, int out_size)
{
    const float* query = (const float*)d_in[0];
    const float* summ  = (const float*)d_in[1];
    const float* templ = (const float*)d_in[2];
    const float* wproj = (const float*)d_in[3];
    const float* bproj = (const float*)d_in[4];
    const float* gamma = (const float*)d_in[5];
    const float* beta  = (const float*)d_in[6];
    const float* glog  = (const float*)d_in[7];
    float* out = (float*)d_out;

    cudaFuncSetAttribute(sims_mma_kernel, cudaFuncAttributeMaxDynamicSharedMemorySize, SIM_TOTAL);
    cudaFuncSetAttribute(fused_mma_kernel, cudaFuncAttributeMaxDynamicSharedMemorySize, SM_TOTAL);

    prep_all_kernel<<<129, 256>>>(wproj, query, glog, out);
    sims_mma_kernel<<<(NPAD + 127) / 128, 256, SIM_TOTAL>>>(summ);
    topk_part_kernel<<<B * PARTS, 128>>>();
    fused_mma_kernel<<<B * KTOP / 2, 512, SM_TOTAL>>>(templ, bproj, gamma, beta, glog, out);
}